// round 2
// baseline (speedup 1.0000x reference)
#include <cuda_runtime.h>

#define NB 32
#define NV 197
#define NT 512
#define ND 768
#define NM (NB*NT)   // 16384

// ---------------- device scratch (no cudaMalloc allowed) ----------------
static __device__ float g_amap[NB*NV*NT];   // 12.9 MB
static __device__ float g_z[NB*NV*NT];      // 12.9 MB  relu(conv(amap))
static __device__ float g_h[NM*ND];         // 50.3 MB
static __device__ float g_ta[NM];
static __device__ float g_va[NB*NV];
static __device__ float g_vcls[NB*ND];
static __device__ float g_tcls[NB*ND];
static __device__ float g_temb[NB*ND];
static __device__ float g_vemb[NB*ND];
static __device__ float g_pred[NM];
static __device__ float g_lossb[NB];
static __device__ float g_keff[9][25];      // 9 border-variant composed 5x5 kernels
static __device__ float g_kbias[9];

__device__ __forceinline__ float wred(float v){
#pragma unroll
    for (int o = 16; o; o >>= 1) v += __shfl_xor_sync(0xffffffffu, v, o);
    return v;
}
__device__ __forceinline__ float sigmoidf(float x){ return 1.f/(1.f + expf(-x)); }

// ---------------- compose conv2(conv1(.)) into 9 variant 5x5 kernels ----------------
// conv1: w1[64,1,3,3], conv2: w2[1,64,3,3], both SAME/zero-pad correlations.
// Output row i=0 means intermediate row -1 is zero-padded -> exclude d1=0 taps (variant ri=0);
// i=V-1 excludes d1=2 (ri=2); same for columns. Bias b1 flows through only the allowed w2 taps.
__global__ void prep_conv_kernel(const float* __restrict__ w1, const float* __restrict__ b1,
                                 const float* __restrict__ w2, const float* __restrict__ b2){
    int tid = threadIdx.x;
    if (tid < 225){
        int var = tid/25, uv = tid%25, u = uv/5, v = uv%5;
        int ri = var/3, rj = var%3;
        float s = 0.f;
        for (int d1=0; d1<3; d1++){
            if ((ri==0 && d1==0) || (ri==2 && d1==2)) continue;
            int d2 = u - d1; if (d2 < 0 || d2 > 2) continue;
            for (int e1=0; e1<3; e1++){
                if ((rj==0 && e1==0) || (rj==2 && e1==2)) continue;
                int e2 = v - e1; if (e2 < 0 || e2 > 2) continue;
                for (int c=0; c<64; c++)
                    s += w2[c*9 + d1*3 + e1] * w1[c*9 + d2*3 + e2];
            }
        }
        g_keff[var][uv] = s;
    } else if (tid < 234){
        int var = tid - 225;
        int ri = var/3, rj = var%3;
        float s = b2[0];
        for (int c=0; c<64; c++){
            float t = 0.f;
            for (int d1=0; d1<3; d1++){
                if ((ri==0 && d1==0) || (ri==2 && d1==2)) continue;
                for (int e1=0; e1<3; e1++){
                    if ((rj==0 && e1==0) || (rj==2 && e1==2)) continue;
                    t += w2[c*9 + d1*3 + e1];
                }
            }
            s += b1[c]*t;
        }
        g_kbias[var] = s;
    }
}

// ---------------- SGEMM 1: amap[b,v,t] = sum_d vision[b,v,d]*text[b,t,d] ----------------
__global__ __launch_bounds__(256,2) void gemm_amap_kernel(const float* __restrict__ vision,
                                                          const float* __restrict__ text){
    __shared__ float As[16][132];
    __shared__ float Bs[16][132];
    int b  = blockIdx.z;
    const float* A  = vision + b*NV*ND;
    const float* Bp = text   + b*NT*ND;
    float* C = g_amap + b*NV*NT;
    int m0 = blockIdx.x*128, n0 = blockIdx.y*128;
    int tid = threadIdx.x;
    int tx = tid & 15, ty = tid >> 4;
    float acc[8][8];
#pragma unroll
    for (int i=0;i<8;i++)
#pragma unroll
        for (int j=0;j<8;j++) acc[i][j] = 0.f;

    for (int k0=0; k0<ND; k0+=16){
#pragma unroll
        for (int l=0; l<8; l++){
            int e = tid + l*256;
            int m = e >> 4, k = e & 15;
            int gm = m0 + m;
            As[k][m] = (gm < NV) ? A[gm*ND + k0 + k] : 0.f;
            Bs[k][m] = Bp[(n0+m)*ND + k0 + k];        // NT=512 multiple of 128
        }
        __syncthreads();
#pragma unroll
        for (int k=0;k<16;k++){
            float4 a0 = *(const float4*)&As[k][ty*8];
            float4 a1 = *(const float4*)&As[k][ty*8+4];
            float4 b0 = *(const float4*)&Bs[k][tx*8];
            float4 b1 = *(const float4*)&Bs[k][tx*8+4];
            float af[8] = {a0.x,a0.y,a0.z,a0.w,a1.x,a1.y,a1.z,a1.w};
            float bf[8] = {b0.x,b0.y,b0.z,b0.w,b1.x,b1.y,b1.z,b1.w};
#pragma unroll
            for (int i=0;i<8;i++)
#pragma unroll
                for (int j=0;j<8;j++) acc[i][j] += af[i]*bf[j];
        }
        __syncthreads();
    }
#pragma unroll
    for (int i=0;i<8;i++){
        int gm = m0 + ty*8 + i;
        if (gm >= NV) continue;
#pragma unroll
        for (int j=0;j<8;j++){
            int gn = n0 + tx*8 + j;
            C[gm*NT + gn] = acc[i][j];
        }
    }
}

// ---------------- fused 5x5 conv + relu ----------------
__global__ void conv_relu_kernel(){
    int p = blockIdx.x*256 + threadIdx.x;       // grid sized exactly
    int b = p / (NV*NT);
    int r = p - b*NV*NT;
    int i = r / NT, j = r - i*NT;
    int ri = (i==0) ? 0 : ((i==NV-1) ? 2 : 1);
    int rj = (j==0) ? 0 : ((j==NT-1) ? 2 : 1);
    const float* Kv = g_keff[ri*3+rj];
    float s = g_kbias[ri*3+rj];
    const float* base = g_amap + b*NV*NT;
#pragma unroll
    for (int u=0;u<5;u++){
        int ii = i + u - 2;
        if (ii < 0 || ii >= NV) continue;
#pragma unroll
        for (int v=0;v<5;v++){
            int jj = j + v - 2;
            if (jj < 0 || jj >= NT) continue;
            s += Kv[u*5+v] * base[ii*NT + jj];
        }
    }
    g_z[p] = fmaxf(s, 0.f);
}

// ---------------- va[b,v] = sigmoid(sum_t z / T) : one warp per row ----------------
__global__ void va_kernel(){
    int w = blockIdx.x*8 + (threadIdx.x >> 5);  // 6304 rows exactly
    int lane = threadIdx.x & 31;
    const float* row = g_z + w*NT;
    float s = 0.f;
    for (int t=lane; t<NT; t+=32) s += row[t];
    s = wred(s);
    if (lane == 0) g_va[w] = sigmoidf(s * (1.f/(float)NT));
}

// ---------------- ta[b,t] = sigmoid(sum_v z / V) : coalesced column sums ----------------
__global__ void ta_kernel(){
    int b = blockIdx.x, tid = threadIdx.x;
    const float* base = g_z + b*NV*NT;
    float a0 = 0.f, a1 = 0.f;
    for (int v=0; v<NV; v++){
        a0 += base[v*NT + tid];
        a1 += base[v*NT + tid + 256];
    }
    g_ta[b*NT + tid]       = sigmoidf(a0 * (1.f/(float)NV));
    g_ta[b*NT + tid + 256] = sigmoidf(a1 * (1.f/(float)NV));
}

// ---------------- vision_CLS / text_CLS ----------------
__global__ void cls_kernel(const float* __restrict__ vision, const float* __restrict__ text){
    int b = blockIdx.x, tid = threadIdx.x;
    float av0=0,av1=0,av2=0, at0=0,at1=0,at2=0;
    const float* vb = vision + b*NV*ND;
    for (int v=0; v<NV; v++){
        float w = g_va[b*NV + v];
        const float* r = vb + v*ND;
        av0 += w*r[tid]; av1 += w*r[tid+256]; av2 += w*r[tid+512];
    }
    const float* tb = text + b*NT*ND;
    for (int t=0; t<NT; t++){
        float w = g_ta[b*NT + t];
        const float* r = tb + t*ND;
        at0 += w*r[tid]; at1 += w*r[tid+256]; at2 += w*r[tid+512];
    }
    g_vcls[b*ND+tid]     = av0*(1.f/(float)NV);
    g_vcls[b*ND+tid+256] = av1*(1.f/(float)NV);
    g_vcls[b*ND+tid+512] = av2*(1.f/(float)NV);
    g_tcls[b*ND+tid]     = at0*(1.f/(float)NT);
    g_tcls[b*ND+tid+256] = at1*(1.f/(float)NT);
    g_tcls[b*ND+tid+512] = at2*(1.f/(float)NT);
}

// ---------------- v_emb/t_emb = fc1(CLS) ----------------
__global__ void emb_kernel(const float* __restrict__ fc1w, const float* __restrict__ fc1b){
    __shared__ float sv[ND], st[ND];
    int b = blockIdx.x, tid = threadIdx.x;
    for (int d=tid; d<ND; d+=256){ sv[d] = g_vcls[b*ND+d]; st[d] = g_tcls[b*ND+d]; }
    __syncthreads();
    int warp = tid >> 5, lane = tid & 31;
    for (int n=warp; n<ND; n+=8){
        const float* wr = fc1w + n*ND;
        float a=0.f, c=0.f;
        for (int k=lane; k<ND; k+=32){ float w = wr[k]; a += w*sv[k]; c += w*st[k]; }
        a = wred(a); c = wred(c);
        if (lane == 0){
            g_vemb[b*ND+n] = a + fc1b[n];
            g_temb[b*ND+n] = c + fc1b[n];
        }
    }
}

// ---------------- SGEMM 2: h[m,n] = relu(sum_k ta[m]*text[m,k]*fc1w[n,k] + b[n]) ----------------
__global__ __launch_bounds__(256,2) void gemm_h_kernel(const float* __restrict__ text,
                                                       const float* __restrict__ fc1w,
                                                       const float* __restrict__ fc1b){
    __shared__ float As[16][132];
    __shared__ float Bs[16][132];
    int m0 = blockIdx.x*128, n0 = blockIdx.y*128;   // M=16384, N=768: exact tiles
    int tid = threadIdx.x;
    int tx = tid & 15, ty = tid >> 4;
    float acc[8][8];
#pragma unroll
    for (int i=0;i<8;i++)
#pragma unroll
        for (int j=0;j<8;j++) acc[i][j] = 0.f;

    for (int k0=0; k0<ND; k0+=16){
#pragma unroll
        for (int l=0; l<8; l++){
            int e = tid + l*256;
            int m = e >> 4, k = e & 15;
            int gm = m0 + m;
            As[k][m] = text[gm*ND + k0 + k] * g_ta[gm];
            Bs[k][m] = fc1w[(n0+m)*ND + k0 + k];
        }
        __syncthreads();
#pragma unroll
        for (int k=0;k<16;k++){
            float4 a0 = *(const float4*)&As[k][ty*8];
            float4 a1 = *(const float4*)&As[k][ty*8+4];
            float4 b0 = *(const float4*)&Bs[k][tx*8];
            float4 b1 = *(const float4*)&Bs[k][tx*8+4];
            float af[8] = {a0.x,a0.y,a0.z,a0.w,a1.x,a1.y,a1.z,a1.w};
            float bf[8] = {b0.x,b0.y,b0.z,b0.w,b1.x,b1.y,b1.z,b1.w};
#pragma unroll
            for (int i=0;i<8;i++)
#pragma unroll
                for (int j=0;j<8;j++) acc[i][j] += af[i]*bf[j];
        }
        __syncthreads();
    }
#pragma unroll
    for (int i=0;i<8;i++){
        int gm = m0 + ty*8 + i;
#pragma unroll
        for (int j=0;j<8;j++){
            int gn = n0 + tx*8 + j;
            g_h[gm*ND + gn] = fmaxf(acc[i][j] + fc1b[gn], 0.f);
        }
    }
}

// ---------------- pred[m] = zmask * (h[m,:] . fc2_w + b) ----------------
__global__ void pred_kernel(const float* __restrict__ fc2w, const float* __restrict__ fc2b,
                            const float* __restrict__ sent){
    int m = blockIdx.x*8 + (threadIdx.x >> 5);
    int lane = threadIdx.x & 31;
    const float* hr = g_h + m*ND;
    float s = 0.f;
    for (int n=lane; n<ND; n+=32) s += fc2w[n]*hr[n];
    s = wred(s);
    if (lane == 0){
        float p = s + fc2b[0];
        if (sent[m] == 0.f) p = 0.f;
        g_pred[m] = p;
    }
}

// ---------------- per-sample masked MSE ----------------
__global__ void textloss_kernel(const float* __restrict__ sent, const int* __restrict__ lens){
    __shared__ float sred[8];
    int b = blockIdx.x, tid = threadIdx.x;
    int len = lens[b];
    float s = 0.f;
    for (int t=tid; t<NT; t+=256){
        if (t < len){
            float d = g_pred[b*NT+t] - sent[b*NT+t];
            s += d*d;
        }
    }
    s = wred(s);
    if ((tid & 31) == 0) sred[tid>>5] = s;
    __syncthreads();
    if (tid < 8){
        float v = sred[tid];
#pragma unroll
        for (int o=4;o;o>>=1) v += __shfl_xor_sync(0xffu, v, o);
        if (tid == 0) g_lossb[b] = v / (float)len;
    }
}

// ---------------- everything small: heads, contrast KL, semantic branch, outputs ----------------
__global__ __launch_bounds__(1024) void final_kernel(const float* __restrict__ fc2w,
                                                     const float* __restrict__ fc2b,
                                                     const float* __restrict__ fw,
                                                     const float* __restrict__ fb,
                                                     float* __restrict__ out){
    __shared__ float s_vs[32], s_ts[32], s_inv_nv[32], s_inv_nt[32];
    __shared__ float s_c[32][32], s_sim[32][32];
    __shared__ float s_crow[32], s_srow[32];
    __shared__ float s_var_v[ND], s_var_t[ND];
    __shared__ float s_red[32];
    __shared__ float s_tile[32][129];
    __shared__ float s_scal[2];

    int tid = threadIdx.x;
    int warp = tid >> 5, lane = tid & 31;

    // (a) per-sample heads + row norms (warp b)
    {
        int b = warp;
        float vs=0.f, ts=0.f, nv=0.f, nt=0.f;
        for (int d=lane; d<ND; d+=32){
            float ve = g_vemb[b*ND+d], te = g_temb[b*ND+d], w = fc2w[d];
            vs += fmaxf(ve,0.f)*w; ts += te*w; nv += ve*ve; nt += te*te;
        }
        vs = wred(vs); ts = wred(ts); nv = wred(nv); nt = wred(nt);
        if (lane == 0){
            s_vs[b] = vs + fc2b[0];
            s_ts[b] = ts + fc2b[0];
            s_inv_nv[b] = 1.f/fmaxf(sqrtf(nv), 1e-12f);
            s_inv_nt[b] = 1.f/fmaxf(sqrtf(nt), 1e-12f);
        }
    }
    __syncthreads();

    // (b) sim[i,j] = exp(cos/0.2) via chunked smem; contrast[i,j]
    int i = tid >> 5, j = tid & 31;
    float dot = 0.f;
    for (int kc=0; kc<ND; kc+=128){
        for (int e=tid; e<32*128; e+=1024){
            int r2 = e >> 7, c2 = e & 127;
            s_tile[r2][c2] = g_temb[r2*ND + kc + c2];
        }
        __syncthreads();
#pragma unroll 8
        for (int c=0;c<128;c++)
            dot += g_vemb[i*ND + kc + c] * s_tile[j][c];
        __syncthreads();
    }
    s_sim[i][j] = expf(dot * s_inv_nv[i] * s_inv_nt[j] * 5.0f);
    s_c[i][j]   = expf(-fabsf(s_vs[i] - s_ts[j]));
    __syncthreads();

    if (tid < 32){
        float cs=0.f, ss=0.f;
        for (int jj=0;jj<32;jj++){ cs += s_c[tid][jj]; ss += s_sim[tid][jj]; }
        s_crow[tid] = cs; s_srow[tid] = ss;
    }
    __syncthreads();

    // (c) KL(contrast || sim) / B
    {
        float cn = s_c[i][j]/s_crow[i];
        float sn = s_sim[i][j]/s_srow[i];
        float term = cn*(logf(cn) - logf(sn));
        term = wred(term);
        if (lane == 0) s_red[warp] = term;
        __syncthreads();
        if (tid < 32){
            float v = wred(s_red[tid]);
            if (tid == 0) out[32] = v * (1.f/32.f);
        }
    }
    __syncthreads();

    // (d) batch variance (ddof=1) of CLS vectors
    if (tid < ND){
        float sx=0.f, sx2=0.f;
        for (int b=0;b<32;b++){ float x = g_vcls[b*ND+tid]; sx += x; sx2 += x*x; }
        s_var_v[tid] = (sx2 - sx*sx*(1.f/32.f))*(1.f/31.f);
        sx=0.f; sx2=0.f;
        for (int b=0;b<32;b++){ float x = g_tcls[b*ND+tid]; sx += x; sx2 += x*x; }
        s_var_t[tid] = (sx2 - sx*sx*(1.f/32.f))*(1.f/31.f);
    }
    __syncthreads();
    {
        float v = (tid < ND) ? s_var_v[tid]*s_var_v[tid] : 0.f;
        v = wred(v);
        if (lane == 0) s_red[warp] = v;
        __syncthreads();
        if (tid < 32){
            float r = wred(s_red[tid]);
            if (tid == 0) s_scal[0] = 1.f/fmaxf(sqrtf(r), 1e-12f);
        }
        __syncthreads();
        float u = (tid < ND) ? s_var_t[tid]*s_var_t[tid] : 0.f;
        u = wred(u);
        if (lane == 0) s_red[warp] = u;
        __syncthreads();
        if (tid < 32){
            float r = wred(s_red[tid]);
            if (tid == 0) s_scal[1] = 1.f/fmaxf(sqrtf(r), 1e-12f);
        }
        __syncthreads();
        if (tid < ND){ s_var_v[tid] *= s_scal[0]; s_var_t[tid] *= s_scal[1]; }
    }
    __syncthreads();

    // (e) fused final head (warp b)
    {
        int b = warp;
        float acc = 0.f;
        for (int d=lane; d<ND; d+=32){
            float sv  = g_vcls[b*ND+d]*(1.f + s_var_v[d]);
            float st2 = g_tcls[b*ND+d]*(1.f + s_var_t[d]);
            float fcls = 0.5f*(sv*st2 + g_vemb[b*ND+d]*g_temb[b*ND+d]);
            acc += fcls*fw[d];
        }
        acc = wred(acc);
        if (lane == 0)
            out[b] = acc + fb[0] + 0.1f*fabsf(s_ts[b] - s_vs[b]) - 0.5f;
    }

    // (f) mean text sentiment loss
    if (tid < 32){
        float v = wred(g_lossb[tid]);
        if (tid == 0) out[33] = v * (1.f/32.f);
    }
}

// ---------------- launch ----------------
extern "C" void kernel_launch(void* const* d_in, const int* in_sizes, int n_in,
                              void* d_out, int out_size){
    const float* vision = (const float*)d_in[0];
    const float* text   = (const float*)d_in[1];
    const float* sent   = (const float*)d_in[2];
    const int*   lens   = (const int*)  d_in[3];
    const float* fc1_w  = (const float*)d_in[4];
    const float* fc1_b  = (const float*)d_in[5];
    const float* fc2_w  = (const float*)d_in[6];
    const float* fc2_b  = (const float*)d_in[7];
    const float* c1w    = (const float*)d_in[8];
    const float* c1b    = (const float*)d_in[9];
    const float* c2w    = (const float*)d_in[10];
    const float* c2b    = (const float*)d_in[11];
    const float* fw     = (const float*)d_in[12];
    const float* fb     = (const float*)d_in[13];
    float* out = (float*)d_out;

    prep_conv_kernel<<<1, 256>>>(c1w, c1b, c2w, c2b);
    gemm_amap_kernel<<<dim3(2,4,NB), 256>>>(vision, text);
    conv_relu_kernel<<<(NB*NV*NT)/256, 256>>>();
    va_kernel<<<(NB*NV)/8, 256>>>();          // 6304/8 = 788
    ta_kernel<<<NB, 256>>>();
    cls_kernel<<<NB, 256>>>(vision, text);
    emb_kernel<<<NB, 256>>>(fc1_w, fc1_b);
    gemm_h_kernel<<<dim3(128,6), 256>>>(text, fc1_w, fc1_b);
    pred_kernel<<<NM/8, 256>>>(fc2_w, fc2_b, sent);
    textloss_kernel<<<NB, 256>>>(sent, lens);
    final_kernel<<<1, 1024>>>(fc2_w, fc2_b, fw, fb, out);
}

// round 3
// speedup vs baseline: 1.4565x; 1.4565x over previous
#include <cuda_runtime.h>
#include <mma.h>
using namespace nvcuda;

#define NB 32
#define NV 197
#define NVP 256          // padded amap row stride (2 x 128 m-tiles)
#define NT 512
#define ND 768
#define NM (NB*NT)       // 16384
#define NNB 6            // n-blocks in gemm_h (768/128)

// ---------------- device scratch (no cudaMalloc allowed) ----------------
static __device__ float g_amap[NB*NVP*NT];  // 16.8 MB (rows 197..255 garbage, never read)
static __device__ float g_z[NB*NV*NT];      // 12.9 MB  relu(conv(amap))
static __device__ float g_ta[NM];
static __device__ float g_va[NB*NV];
static __device__ float g_vcls[NB*ND];
static __device__ float g_tcls[NB*ND];
static __device__ float g_temb[NB*ND];
static __device__ float g_vemb[NB*ND];
static __device__ float g_predpart[NNB*NM];
static __device__ float g_lossb[NB];
static __device__ float g_keff[9][25];
static __device__ float g_kbias[9];

__device__ __forceinline__ float wred(float v){
#pragma unroll
    for (int o = 16; o; o >>= 1) v += __shfl_xor_sync(0xffffffffu, v, o);
    return v;
}
__device__ __forceinline__ float sigmoidf(float x){ return 1.f/(1.f + expf(-x)); }

// ---------------- compose conv2(conv1(.)) into 9 border-variant 5x5 kernels ----------------
__global__ void prep_conv_kernel(const float* __restrict__ w1, const float* __restrict__ b1,
                                 const float* __restrict__ w2, const float* __restrict__ b2){
    int tid = threadIdx.x;
    if (tid < 225){
        int var = tid/25, uv = tid%25, u = uv/5, v = uv%5;
        int ri = var/3, rj = var%3;
        float s = 0.f;
        for (int d1=0; d1<3; d1++){
            if ((ri==0 && d1==0) || (ri==2 && d1==2)) continue;
            int d2 = u - d1; if (d2 < 0 || d2 > 2) continue;
            for (int e1=0; e1<3; e1++){
                if ((rj==0 && e1==0) || (rj==2 && e1==2)) continue;
                int e2 = v - e1; if (e2 < 0 || e2 > 2) continue;
                for (int c=0; c<64; c++)
                    s += w2[c*9 + d1*3 + e1] * w1[c*9 + d2*3 + e2];
            }
        }
        g_keff[var][uv] = s;
    } else if (tid < 234){
        int var = tid - 225;
        int ri = var/3, rj = var%3;
        float s = b2[0];
        for (int c=0; c<64; c++){
            float t = 0.f;
            for (int d1=0; d1<3; d1++){
                if ((ri==0 && d1==0) || (ri==2 && d1==2)) continue;
                for (int e1=0; e1<3; e1++){
                    if ((rj==0 && e1==0) || (rj==2 && e1==2)) continue;
                    t += w2[c*9 + d1*3 + e1];
                }
            }
            s += b1[c]*t;
        }
        g_kbias[var] = s;
    }
}

// ---------------- TF32 GEMM 1: amap[b,v,t] = sum_d vision[b,v,d]*text[b,t,d] ----------------
__global__ __launch_bounds__(256,2) void gemm_amap_kernel(const float* __restrict__ vision,
                                                          const float* __restrict__ text){
    __shared__ float smem_pool[2*128*36];
    float* As = smem_pool;
    float* Bs = smem_pool + 128*36;
    int b  = blockIdx.z;
    const float* A  = vision + b*NV*ND;
    const float* Bp = text   + b*NT*ND;
    int m0 = blockIdx.x*128, n0 = blockIdx.y*128;
    int tid = threadIdx.x, wid = tid >> 5;
    int warp_m = wid >> 1, warp_n = wid & 1;

    wmma::fragment<wmma::accumulator,16,16,8,float> acc[2][4];
#pragma unroll
    for (int mf=0;mf<2;mf++)
#pragma unroll
        for (int nf=0;nf<4;nf++) wmma::fill_fragment(acc[mf][nf], 0.f);

    for (int k0=0; k0<ND; k0+=32){
#pragma unroll
        for (int l=0; l<4; l++){
            int e = tid + l*256;              // float4 index 0..1023
            int row = e >> 3, c4 = e & 7;
            int gm = m0 + row; if (gm > NV-1) gm = NV-1;   // clamp; rows >=197 never read
            *(float4*)&As[row*36 + c4*4] = *(const float4*)&A[gm*ND + k0 + c4*4];
            *(float4*)&Bs[row*36 + c4*4] = *(const float4*)&Bp[(n0+row)*ND + k0 + c4*4];
        }
        __syncthreads();
#pragma unroll
        for (int ks=0; ks<4; ks++){
            wmma::fragment<wmma::matrix_a,16,16,8,wmma::precision::tf32,wmma::row_major> af[2];
            wmma::fragment<wmma::matrix_b,16,16,8,wmma::precision::tf32,wmma::col_major> bf[4];
#pragma unroll
            for (int mf=0;mf<2;mf++){
                wmma::load_matrix_sync(af[mf], &As[(warp_m*32+mf*16)*36 + ks*8], 36);
#pragma unroll
                for (int t=0;t<af[mf].num_elements;t++) af[mf].x[t] = wmma::__float_to_tf32(af[mf].x[t]);
            }
#pragma unroll
            for (int nf=0;nf<4;nf++){
                wmma::load_matrix_sync(bf[nf], &Bs[(warp_n*64+nf*16)*36 + ks*8], 36);
#pragma unroll
                for (int t=0;t<bf[nf].num_elements;t++) bf[nf].x[t] = wmma::__float_to_tf32(bf[nf].x[t]);
            }
#pragma unroll
            for (int mf=0;mf<2;mf++)
#pragma unroll
                for (int nf=0;nf<4;nf++)
                    wmma::mma_sync(acc[mf][nf], af[mf], bf[nf], acc[mf][nf]);
        }
        __syncthreads();
    }
    float* C = g_amap + b*NVP*NT;
#pragma unroll
    for (int mf=0;mf<2;mf++)
#pragma unroll
        for (int nf=0;nf<4;nf++)
            wmma::store_matrix_sync(&C[(m0+warp_m*32+mf*16)*NT + n0+warp_n*64+nf*16],
                                    acc[mf][nf], NT, wmma::mem_row_major);
}

// ---------------- fused 5x5 conv + relu (reads padded amap) ----------------
__global__ void conv_relu_kernel(){
    int p = blockIdx.x*256 + threadIdx.x;
    int b = p / (NV*NT);
    int r = p - b*NV*NT;
    int i = r / NT, j = r - i*NT;
    int ri = (i==0) ? 0 : ((i==NV-1) ? 2 : 1);
    int rj = (j==0) ? 0 : ((j==NT-1) ? 2 : 1);
    const float* Kv = g_keff[ri*3+rj];
    float s = g_kbias[ri*3+rj];
    const float* base = g_amap + b*NVP*NT;
#pragma unroll
    for (int u=0;u<5;u++){
        int ii = i + u - 2;
        if (ii < 0 || ii >= NV) continue;
#pragma unroll
        for (int v=0;v<5;v++){
            int jj = j + v - 2;
            if (jj < 0 || jj >= NT) continue;
            s += Kv[u*5+v] * base[ii*NT + jj];
        }
    }
    g_z[p] = fmaxf(s, 0.f);
}

// ---------------- va[b,v] = sigmoid(sum_t z / T) ----------------
__global__ void va_kernel(){
    int w = blockIdx.x*8 + (threadIdx.x >> 5);
    int lane = threadIdx.x & 31;
    const float* row = g_z + w*NT;
    float s = 0.f;
    for (int t=lane; t<NT; t+=32) s += row[t];
    s = wred(s);
    if (lane == 0) g_va[w] = sigmoidf(s * (1.f/(float)NT));
}

// ---------------- ta[b,t] = sigmoid(sum_v z / V) : grid (NB,2) ----------------
__global__ void ta_kernel(){
    int b = blockIdx.x;
    int t = blockIdx.y*256 + threadIdx.x;
    const float* base = g_z + b*NV*NT + t;
    float a = 0.f;
#pragma unroll 4
    for (int v=0; v<NV; v++) a += base[v*NT];
    g_ta[b*NT + t] = sigmoidf(a * (1.f/(float)NV));
}

// ---------------- vision_CLS / text_CLS : grid (NB,3) ----------------
__global__ void cls_kernel(const float* __restrict__ vision, const float* __restrict__ text){
    int b = blockIdx.x;
    int d = blockIdx.y*256 + threadIdx.x;
    float av = 0.f, at = 0.f;
    const float* vb = vision + b*NV*ND + d;
#pragma unroll 4
    for (int v=0; v<NV; v++) av += g_va[b*NV+v] * vb[v*ND];
    const float* tb = text + b*NT*ND + d;
#pragma unroll 4
    for (int t=0; t<NT; t++) at += g_ta[b*NT+t] * tb[t*ND];
    g_vcls[b*ND+d] = av * (1.f/(float)NV);
    g_tcls[b*ND+d] = at * (1.f/(float)NT);
}

// ---------------- v_emb/t_emb = fc1(CLS)  (fp32 — feeds the KL/log path) ----------------
__global__ void emb_kernel(const float* __restrict__ fc1w, const float* __restrict__ fc1b){
    __shared__ float sv[ND], st[ND];
    int b = blockIdx.x, tid = threadIdx.x;
    for (int d=tid; d<ND; d+=256){ sv[d] = g_vcls[b*ND+d]; st[d] = g_tcls[b*ND+d]; }
    __syncthreads();
    int warp = tid >> 5, lane = tid & 31;
    for (int n=warp; n<ND; n+=8){
        const float* wr = fc1w + n*ND;
        float a=0.f, c=0.f;
        for (int k=lane; k<ND; k+=32){ float w = wr[k]; a += w*sv[k]; c += w*st[k]; }
        a = wred(a); c = wred(c);
        if (lane == 0){
            g_vemb[b*ND+n] = a + fc1b[n];
            g_temb[b*ND+n] = c + fc1b[n];
        }
    }
}

// ---- TF32 GEMM 2 + fused pred epilogue:
//      predpart[nblk][m] = sum_{n in blk} relu( (ta[m]*text[m,:]) . fc1w[n,:] + b1[n] ) * fc2w[n]
__global__ __launch_bounds__(256,2) void gemm_h_kernel(const float* __restrict__ text,
                                                       const float* __restrict__ fc1w,
                                                       const float* __restrict__ fc1b,
                                                       const float* __restrict__ fc2w){
    __shared__ float smem_pool[2*128*36];   // >= 64*132 epilogue buffer
    float* As = smem_pool;
    float* Bs = smem_pool + 128*36;
    int m0 = blockIdx.x*128, n0 = blockIdx.y*128;
    int tid = threadIdx.x, wid = tid >> 5;
    int warp_m = wid >> 1, warp_n = wid & 1;

    wmma::fragment<wmma::accumulator,16,16,8,float> acc[2][4];
#pragma unroll
    for (int mf=0;mf<2;mf++)
#pragma unroll
        for (int nf=0;nf<4;nf++) wmma::fill_fragment(acc[mf][nf], 0.f);

    for (int k0=0; k0<ND; k0+=32){
#pragma unroll
        for (int l=0; l<4; l++){
            int e = tid + l*256;
            int row = e >> 3, c4 = e & 7;
            int gm = m0 + row;
            float4 a4 = *(const float4*)&text[gm*ND + k0 + c4*4];
            float sc = g_ta[gm];
            a4.x *= sc; a4.y *= sc; a4.z *= sc; a4.w *= sc;
            *(float4*)&As[row*36 + c4*4] = a4;
            *(float4*)&Bs[row*36 + c4*4] = *(const float4*)&fc1w[(n0+row)*ND + k0 + c4*4];
        }
        __syncthreads();
#pragma unroll
        for (int ks=0; ks<4; ks++){
            wmma::fragment<wmma::matrix_a,16,16,8,wmma::precision::tf32,wmma::row_major> af[2];
            wmma::fragment<wmma::matrix_b,16,16,8,wmma::precision::tf32,wmma::col_major> bf[4];
#pragma unroll
            for (int mf=0;mf<2;mf++){
                wmma::load_matrix_sync(af[mf], &As[(warp_m*32+mf*16)*36 + ks*8], 36);
#pragma unroll
                for (int t=0;t<af[mf].num_elements;t++) af[mf].x[t] = wmma::__float_to_tf32(af[mf].x[t]);
            }
#pragma unroll
            for (int nf=0;nf<4;nf++){
                wmma::load_matrix_sync(bf[nf], &Bs[(warp_n*64+nf*16)*36 + ks*8], 36);
#pragma unroll
                for (int t=0;t<bf[nf].num_elements;t++) bf[nf].x[t] = wmma::__float_to_tf32(bf[nf].x[t]);
            }
#pragma unroll
            for (int mf=0;mf<2;mf++)
#pragma unroll
                for (int nf=0;nf<4;nf++)
                    wmma::mma_sync(acc[mf][nf], af[mf], bf[nf], acc[mf][nf]);
        }
        __syncthreads();
    }

    // fused epilogue: bias + relu + dot(fc2w) over this block's 128 columns
    float* buf = smem_pool;   // 64 rows x 132
    int row = tid >> 2, q = tid & 3;
#pragma unroll
    for (int half=0; half<2; half++){
        if ((warp_m >> 1) == half){
            int rbase = (warp_m & 1)*32;
#pragma unroll
            for (int mf=0;mf<2;mf++)
#pragma unroll
                for (int nf=0;nf<4;nf++)
                    wmma::store_matrix_sync(&buf[(rbase+mf*16)*132 + warp_n*64+nf*16],
                                            acc[mf][nf], 132, wmma::mem_row_major);
        }
        __syncthreads();
        float s = 0.f;
        int cbase = q*32;
#pragma unroll
        for (int c=0;c<32;c++){
            int gn = n0 + cbase + c;
            s += fmaxf(buf[row*132 + cbase + c] + fc1b[gn], 0.f) * fc2w[gn];
        }
        s += __shfl_down_sync(0xffffffffu, s, 2);
        s += __shfl_down_sync(0xffffffffu, s, 1);
        if (q == 0) g_predpart[blockIdx.y*NM + m0 + half*64 + row] = s;
        __syncthreads();
    }
}

// ---------------- per-sample masked MSE, pred assembled from partials ----------------
__global__ void textloss_kernel(const float* __restrict__ sent, const int* __restrict__ lens,
                                const float* __restrict__ fc2b){
    __shared__ float sred[8];
    int b = blockIdx.x, tid = threadIdx.x;
    int len = lens[b];
    float s = 0.f;
    for (int t=tid; t<NT; t+=256){
        int m = b*NT + t;
        float p = fc2b[0];
#pragma unroll
        for (int pp=0; pp<NNB; pp++) p += g_predpart[pp*NM + m];
        if (sent[m] == 0.f) p = 0.f;
        if (t < len){
            float d = p - sent[m];
            s += d*d;
        }
    }
    s = wred(s);
    if ((tid & 31) == 0) sred[tid>>5] = s;
    __syncthreads();
    if (tid < 8){
        float v = sred[tid];
#pragma unroll
        for (int o=4;o;o>>=1) v += __shfl_xor_sync(0xffu, v, o);
        if (tid == 0) g_lossb[b] = v / (float)len;
    }
}

// ---------------- heads, contrast KL, semantic branch, outputs ----------------
__global__ __launch_bounds__(1024) void final_kernel(const float* __restrict__ fc2w,
                                                     const float* __restrict__ fc2b,
                                                     const float* __restrict__ fw,
                                                     const float* __restrict__ fb,
                                                     float* __restrict__ out){
    __shared__ float s_vs[32], s_ts[32], s_inv_nv[32], s_inv_nt[32];
    __shared__ float s_c[32][32], s_sim[32][32];
    __shared__ float s_crow[32], s_srow[32];
    __shared__ float s_var_v[ND], s_var_t[ND];
    __shared__ float s_red[32];
    __shared__ float s_tile[32][129];
    __shared__ float s_scal[2];

    int tid = threadIdx.x;
    int warp = tid >> 5, lane = tid & 31;

    {
        int b = warp;
        float vs=0.f, ts=0.f, nv=0.f, nt=0.f;
        for (int d=lane; d<ND; d+=32){
            float ve = g_vemb[b*ND+d], te = g_temb[b*ND+d], w = fc2w[d];
            vs += fmaxf(ve,0.f)*w; ts += te*w; nv += ve*ve; nt += te*te;
        }
        vs = wred(vs); ts = wred(ts); nv = wred(nv); nt = wred(nt);
        if (lane == 0){
            s_vs[b] = vs + fc2b[0];
            s_ts[b] = ts + fc2b[0];
            s_inv_nv[b] = 1.f/fmaxf(sqrtf(nv), 1e-12f);
            s_inv_nt[b] = 1.f/fmaxf(sqrtf(nt), 1e-12f);
        }
    }
    __syncthreads();

    int i = tid >> 5, j = tid & 31;
    float dot = 0.f;
    for (int kc=0; kc<ND; kc+=128){
        for (int e=tid; e<32*128; e+=1024){
            int r2 = e >> 7, c2 = e & 127;
            s_tile[r2][c2] = g_temb[r2*ND + kc + c2];
        }
        __syncthreads();
#pragma unroll 8
        for (int c=0;c<128;c++)
            dot += g_vemb[i*ND + kc + c] * s_tile[j][c];
        __syncthreads();
    }
    s_sim[i][j] = expf(dot * s_inv_nv[i] * s_inv_nt[j] * 5.0f);
    s_c[i][j]   = expf(-fabsf(s_vs[i] - s_ts[j]));
    __syncthreads();

    if (tid < 32){
        float cs=0.f, ss=0.f;
        for (int jj=0;jj<32;jj++){ cs += s_c[tid][jj]; ss += s_sim[tid][jj]; }
        s_crow[tid] = cs; s_srow[tid] = ss;
    }
    __syncthreads();

    {
        float cn = s_c[i][j]/s_crow[i];
        float sn = s_sim[i][j]/s_srow[i];
        float term = cn*(logf(cn) - logf(sn));
        term = wred(term);
        if (lane == 0) s_red[warp] = term;
        __syncthreads();
        if (tid < 32){
            float v = wred(s_red[tid]);
            if (tid == 0) out[32] = v * (1.f/32.f);
        }
    }
    __syncthreads();

    if (tid < ND){
        float sx=0.f, sx2=0.f;
        for (int b=0;b<32;b++){ float x = g_vcls[b*ND+tid]; sx += x; sx2 += x*x; }
        s_var_v[tid] = (sx2 - sx*sx*(1.f/32.f))*(1.f/31.f);
        sx=0.f; sx2=0.f;
        for (int b=0;b<32;b++){ float x = g_tcls[b*ND+tid]; sx += x; sx2 += x*x; }
        s_var_t[tid] = (sx2 - sx*sx*(1.f/32.f))*(1.f/31.f);
    }
    __syncthreads();
    {
        float v = (tid < ND) ? s_var_v[tid]*s_var_v[tid] : 0.f;
        v = wred(v);
        if (lane == 0) s_red[warp] = v;
        __syncthreads();
        if (tid < 32){
            float r = wred(s_red[tid]);
            if (tid == 0) s_scal[0] = 1.f/fmaxf(sqrtf(r), 1e-12f);
        }
        __syncthreads();
        float u = (tid < ND) ? s_var_t[tid]*s_var_t[tid] : 0.f;
        u = wred(u);
        if (lane == 0) s_red[warp] = u;
        __syncthreads();
        if (tid < 32){
            float r = wred(s_red[tid]);
            if (tid == 0) s_scal[1] = 1.f/fmaxf(sqrtf(r), 1e-12f);
        }
        __syncthreads();
        if (tid < ND){ s_var_v[tid] *= s_scal[0]; s_var_t[tid] *= s_scal[1]; }
    }
    __syncthreads();

    {
        int b = warp;
        float acc = 0.f;
        for (int d=lane; d<ND; d+=32){
            float sv  = g_vcls[b*ND+d]*(1.f + s_var_v[d]);
            float st2 = g_tcls[b*ND+d]*(1.f + s_var_t[d]);
            float fcls = 0.5f*(sv*st2 + g_vemb[b*ND+d]*g_temb[b*ND+d]);
            acc += fcls*fw[d];
        }
        acc = wred(acc);
        if (lane == 0)
            out[b] = acc + fb[0] + 0.1f*fabsf(s_ts[b] - s_vs[b]) - 0.5f;
    }

    if (tid < 32){
        float v = wred(g_lossb[tid]);
        if (tid == 0) out[33] = v * (1.f/32.f);
    }
}

// ---------------- launch ----------------
extern "C" void kernel_launch(void* const* d_in, const int* in_sizes, int n_in,
                              void* d_out, int out_size){
    const float* vision = (const float*)d_in[0];
    const float* text   = (const float*)d_in[1];
    const float* sent   = (const float*)d_in[2];
    const int*   lens   = (const int*)  d_in[3];
    const float* fc1_w  = (const float*)d_in[4];
    const float* fc1_b  = (const float*)d_in[5];
    const float* fc2_w  = (const float*)d_in[6];
    const float* fc2_b  = (const float*)d_in[7];
    const float* c1w    = (const float*)d_in[8];
    const float* c1b    = (const float*)d_in[9];
    const float* c2w    = (const float*)d_in[10];
    const float* c2b    = (const float*)d_in[11];
    const float* fw     = (const float*)d_in[12];
    const float* fb     = (const float*)d_in[13];
    float* out = (float*)d_out;

    prep_conv_kernel<<<1, 256>>>(c1w, c1b, c2w, c2b);
    gemm_amap_kernel<<<dim3(2,4,NB), 256>>>(vision, text);
    conv_relu_kernel<<<(NB*NV*NT)/256, 256>>>();
    va_kernel<<<(NB*NV)/8, 256>>>();
    ta_kernel<<<dim3(NB,2), 256>>>();
    cls_kernel<<<dim3(NB,3), 256>>>(vision, text);
    emb_kernel<<<NB, 256>>>(fc1_w, fc1_b);
    gemm_h_kernel<<<dim3(128,NNB), 256>>>(text, fc1_w, fc1_b, fc2_w);
    textloss_kernel<<<NB, 256>>>(sent, lens, fc2_b);
    final_kernel<<<1, 1024>>>(fc2_w, fc2_b, fw, fb, out);
}

// round 5
// speedup vs baseline: 1.8115x; 1.2438x over previous
#include <cuda_runtime.h>
#include <cstdint>
#include <mma.h>
using namespace nvcuda;

#define NB 32
#define NV 197
#define NVP 256          // padded amap row stride (2 x 128 m-tiles)
#define NT 512
#define ND 768
#define NM (NB*NT)       // 16384
#define NNB 6            // n-blocks in gemm_h (768/128)
#define NCH 13           // conv row-chunks of 16 (13*16=208 >= 197)

// ---------------- device scratch (no cudaMalloc allowed) ----------------
static __device__ float g_amap[NB*NVP*NT];      // 16.8 MB
static __device__ float g_tapart[NCH*NB*NT];    // conv column partials
static __device__ float g_ta[NM];
static __device__ float g_va[NB*NV];
static __device__ float g_vcls[NB*ND];
static __device__ float g_tcls[NB*ND];
static __device__ float g_temb[NB*ND];
static __device__ float g_vemb[NB*ND];
static __device__ float g_predpart[NNB*NM];
static __device__ float g_lossb[NB];
static __device__ float g_keff[9][25];
static __device__ float g_kbias[9];

__device__ __forceinline__ float wred(float v){
#pragma unroll
    for (int o = 16; o; o >>= 1) v += __shfl_xor_sync(0xffffffffu, v, o);
    return v;
}
__device__ __forceinline__ float sigmoidf(float x){ return 1.f/(1.f + expf(-x)); }

// ---- cp.async helpers ----
__device__ __forceinline__ void cp16(void* s, const void* g){
    unsigned int sa = (unsigned int)__cvta_generic_to_shared(s);
    asm volatile("cp.async.cg.shared.global [%0], [%1], 16;" :: "r"(sa), "l"(g));
}
__device__ __forceinline__ void cp_commit(){ asm volatile("cp.async.commit_group;"); }
template<int N> __device__ __forceinline__ void cp_wait(){
    asm volatile("cp.async.wait_group %0;" :: "n"(N));
}

// ---------------- compose conv2(conv1(.)) into 9 border-variant 5x5 kernels ----------------
__global__ void prep_conv_kernel(const float* __restrict__ w1, const float* __restrict__ b1,
                                 const float* __restrict__ w2, const float* __restrict__ b2){
    int tid = threadIdx.x;
    if (tid < 225){
        int var = tid/25, uv = tid%25, u = uv/5, v = uv%5;
        int ri = var/3, rj = var%3;
        float s = 0.f;
        for (int d1=0; d1<3; d1++){
            if ((ri==0 && d1==0) || (ri==2 && d1==2)) continue;
            int d2 = u - d1; if (d2 < 0 || d2 > 2) continue;
            for (int e1=0; e1<3; e1++){
                if ((rj==0 && e1==0) || (rj==2 && e1==2)) continue;
                int e2 = v - e1; if (e2 < 0 || e2 > 2) continue;
                for (int c=0; c<64; c++)
                    s += w2[c*9 + d1*3 + e1] * w1[c*9 + d2*3 + e2];
            }
        }
        g_keff[var][uv] = s;
    } else if (tid < 234){
        int var = tid - 225;
        int ri = var/3, rj = var%3;
        float s = b2[0];
        for (int c=0; c<64; c++){
            float t = 0.f;
            for (int d1=0; d1<3; d1++){
                if ((ri==0 && d1==0) || (ri==2 && d1==2)) continue;
                for (int e1=0; e1<3; e1++){
                    if ((rj==0 && e1==0) || (rj==2 && e1==2)) continue;
                    t += w2[c*9 + d1*3 + e1];
                }
            }
            s += b1[c]*t;
        }
        g_kbias[var] = s;
    }
}

// ============ TF32 GEMM 1 (cp.async 2-stage): amap[b,v,t] = vision[b,v,:].text[b,t,:] ============
__global__ __launch_bounds__(256,2) void gemm_amap_kernel(const float* __restrict__ vision,
                                                          const float* __restrict__ text){
    __shared__ float sm[2][2][128][20];   // [stage][A/B][row][k(16)+pad4]
    int b  = blockIdx.z;
    const float* A  = vision + b*NV*ND;
    const float* Bp = text   + b*NT*ND;
    int m0 = blockIdx.x*128, n0 = blockIdx.y*128;
    int tid = threadIdx.x, wid = tid >> 5;
    int warp_m = wid >> 1, warp_n = wid & 1;
    int lrow = tid >> 2, lc4 = tid & 3;       // per-thread load coords

    wmma::fragment<wmma::accumulator,16,16,8,float> acc[2][4];
#pragma unroll
    for (int mf=0;mf<2;mf++)
#pragma unroll
        for (int nf=0;nf<4;nf++) wmma::fill_fragment(acc[mf][nf], 0.f);

    const int NKT = ND/16;   // 48
    {
        int gm = m0 + lrow; if (gm > NV-1) gm = NV-1;
        cp16(&sm[0][0][lrow][lc4*4],     &A [gm*ND + lc4*4]);
        cp16(&sm[0][1][lrow][lc4*4],     &Bp[(n0+lrow)*ND + lc4*4]);
        int gm2 = m0 + lrow + 64; if (gm2 > NV-1) gm2 = NV-1;
        cp16(&sm[0][0][lrow+64][lc4*4],  &A [gm2*ND + lc4*4]);
        cp16(&sm[0][1][lrow+64][lc4*4],  &Bp[(n0+lrow+64)*ND + lc4*4]);
        cp_commit();
    }
    for (int kt=0; kt<NKT; kt++){
        if (kt+1 < NKT){
            int k0 = (kt+1)*16, s = (kt+1)&1;
            int gm = m0 + lrow; if (gm > NV-1) gm = NV-1;
            cp16(&sm[s][0][lrow][lc4*4],     &A [gm*ND + k0 + lc4*4]);
            cp16(&sm[s][1][lrow][lc4*4],     &Bp[(n0+lrow)*ND + k0 + lc4*4]);
            int gm2 = m0 + lrow + 64; if (gm2 > NV-1) gm2 = NV-1;
            cp16(&sm[s][0][lrow+64][lc4*4],  &A [gm2*ND + k0 + lc4*4]);
            cp16(&sm[s][1][lrow+64][lc4*4],  &Bp[(n0+lrow+64)*ND + k0 + lc4*4]);
            cp_commit();
            cp_wait<1>();
        } else cp_wait<0>();
        __syncthreads();
        int s = kt & 1;
#pragma unroll
        for (int ks=0; ks<2; ks++){
            wmma::fragment<wmma::matrix_a,16,16,8,wmma::precision::tf32,wmma::row_major> af[2];
            wmma::fragment<wmma::matrix_b,16,16,8,wmma::precision::tf32,wmma::col_major> bf[4];
#pragma unroll
            for (int mf=0;mf<2;mf++)
                wmma::load_matrix_sync(af[mf], &sm[s][0][warp_m*32+mf*16][ks*8], 20);
#pragma unroll
            for (int nf=0;nf<4;nf++)
                wmma::load_matrix_sync(bf[nf], &sm[s][1][warp_n*64+nf*16][ks*8], 20);
#pragma unroll
            for (int mf=0;mf<2;mf++)
#pragma unroll
                for (int nf=0;nf<4;nf++)
                    wmma::mma_sync(acc[mf][nf], af[mf], bf[nf], acc[mf][nf]);
        }
        __syncthreads();
    }
    float* C = g_amap + b*NVP*NT;
#pragma unroll
    for (int mf=0;mf<2;mf++)
#pragma unroll
        for (int nf=0;nf<4;nf++)
            wmma::store_matrix_sync(&C[(m0+warp_m*32+mf*16)*NT + n0+warp_n*64+nf*16],
                                    acc[mf][nf], NT, wmma::mem_row_major);
}

// ============ fused 5x5 conv + relu + row-sums (va) + column partials (ta) ============
__global__ __launch_bounds__(256) void conv_fused_kernel(){
    __shared__ float smz[20][NT];
    __shared__ float kv[9][25];
    __shared__ float kb[9];
    __shared__ float rowred[16][8];
    int c = blockIdx.x;              // row chunk 0..12
    int b = blockIdx.y;
    int tid = threadIdx.x;
    int warp = tid >> 5, lane = tid & 31;
    if (tid < 225) ((float*)kv)[tid] = ((const float*)g_keff)[tid];
    else if (tid >= 240 && tid < 249) kb[tid-240] = g_kbias[tid-240];

    int i0 = c*16;
    const float* base = g_amap + b*NVP*NT;
#pragma unroll
    for (int l=0; l<10; l++){
        int e = tid + l*256;
        int rr = e >> 7, c4 = e & 127;
        int gi = i0 - 2 + rr;
        float4 v = make_float4(0.f,0.f,0.f,0.f);
        if (gi >= 0 && gi < NV) v = *(const float4*)&base[gi*NT + c4*4];
        *(float4*)&smz[rr][c4*4] = v;
    }
    __syncthreads();

    float colsum0 = 0.f, colsum1 = 0.f;
    float rowpart[16];
#pragma unroll
    for (int rr=0; rr<16; rr++){
        int i = i0 + rr;
        float rs = 0.f;
        if (i < NV){
            int ri = (i==0) ? 0 : ((i==NV-1) ? 2 : 1);
#pragma unroll
            for (int jj=0; jj<2; jj++){
                int j = tid + jj*256;
                int rj = (j==0) ? 0 : ((j==NT-1) ? 2 : 1);
                int var = ri*3 + rj;
                float s = kb[var];
                const float* kp = kv[var];
#pragma unroll
                for (int u=0; u<5; u++){
#pragma unroll
                    for (int v=0; v<5; v++){
                        int j2 = j + v - 2;
                        if (j2 >= 0 && j2 < NT)
                            s += kp[u*5+v] * smz[rr+u][j2];
                    }
                }
                s = fmaxf(s, 0.f);
                if (jj == 0) colsum0 += s; else colsum1 += s;
                rs += s;
            }
        }
        rowpart[rr] = rs;
    }
    // column partials
    float* tp = g_tapart + (c*NB + b)*NT;
    tp[tid]       = colsum0;
    tp[tid + 256] = colsum1;
    // row sums -> va
#pragma unroll
    for (int rr=0; rr<16; rr++){
        float v = wred(rowpart[rr]);
        if (lane == 0) rowred[rr][warp] = v;
    }
    __syncthreads();
    if (tid < 128){
        int rr = tid >> 3, slot = tid & 7;
        float v = rowred[rr][slot];
        v += __shfl_down_sync(0xffffffffu, v, 4, 8);
        v += __shfl_down_sync(0xffffffffu, v, 2, 8);
        v += __shfl_down_sync(0xffffffffu, v, 1, 8);
        if (slot == 0){
            int gi = i0 + rr;
            if (gi < NV) g_va[b*NV + gi] = sigmoidf(v * (1.f/(float)NT));
        }
    }
}

// ---------------- ta finalize: sum 13 partials ----------------
__global__ void ta_final_kernel(){
    int b = blockIdx.x;
    int t = blockIdx.y*256 + threadIdx.x;
    float s = 0.f;
#pragma unroll
    for (int c=0; c<NCH; c++) s += g_tapart[(c*NB + b)*NT + t];
    g_ta[b*NT + t] = sigmoidf(s * (1.f/(float)NV));
}

// ---------------- vision_CLS / text_CLS : grid (NB,3) ----------------
__global__ void cls_kernel(const float* __restrict__ vision, const float* __restrict__ text){
    int b = blockIdx.x;
    int d = blockIdx.y*256 + threadIdx.x;
    float av = 0.f, at = 0.f;
    const float* vb = vision + b*NV*ND + d;
#pragma unroll 4
    for (int v=0; v<NV; v++) av += g_va[b*NV+v] * vb[v*ND];
    const float* tb = text + b*NT*ND + d;
#pragma unroll 4
    for (int t=0; t<NT; t++) at += g_ta[b*NT+t] * tb[t*ND];
    g_vcls[b*ND+d] = av * (1.f/(float)NV);
    g_tcls[b*ND+d] = at * (1.f/(float)NT);
}

// ---------------- v_emb/t_emb = fc1(CLS)  (fp32, grid (NB,8)) ----------------
__global__ void emb_kernel(const float* __restrict__ fc1w, const float* __restrict__ fc1b){
    __shared__ float sv[ND], st[ND];
    int b = blockIdx.x, tid = threadIdx.x;
    int warp = tid >> 5, lane = tid & 31;
    for (int d=tid; d<ND; d+=256){ sv[d] = g_vcls[b*ND+d]; st[d] = g_tcls[b*ND+d]; }
    __syncthreads();
    int n0 = blockIdx.y*96 + warp*12;
#pragma unroll
    for (int k=0; k<12; k++){
        int n = n0 + k;
        const float* wr = fc1w + n*ND;
        float a=0.f, cc=0.f;
        for (int d=lane; d<ND; d+=32){ float w = wr[d]; a += w*sv[d]; cc += w*st[d]; }
        a = wred(a); cc = wred(cc);
        if (lane == 0){
            g_vemb[b*ND+n] = a + fc1b[n];
            g_temb[b*ND+n] = cc + fc1b[n];
        }
    }
}

// ============ TF32 GEMM 2 (cp.async 2-stage) + fused pred epilogue ============
// predpart[nblk][m] = sum_{n in blk} relu( ta[m]*(text[m,:].fc1w[n,:]) + b1[n] ) * fc2w[n]
__global__ __launch_bounds__(256,2) void gemm_h_kernel(const float* __restrict__ text,
                                                       const float* __restrict__ fc1w,
                                                       const float* __restrict__ fc1b,
                                                       const float* __restrict__ fc2w){
    __shared__ float sm[2][2][128][20];
    int m0 = blockIdx.x*128, n0 = blockIdx.y*128;
    int tid = threadIdx.x, wid = tid >> 5;
    int warp_m = wid >> 1, warp_n = wid & 1;
    int lrow = tid >> 2, lc4 = tid & 3;

    wmma::fragment<wmma::accumulator,16,16,8,float> acc[2][4];
#pragma unroll
    for (int mf=0;mf<2;mf++)
#pragma unroll
        for (int nf=0;nf<4;nf++) wmma::fill_fragment(acc[mf][nf], 0.f);

    const int NKT = ND/16;
    {
        cp16(&sm[0][0][lrow][lc4*4],    &text[(m0+lrow)*ND + lc4*4]);
        cp16(&sm[0][1][lrow][lc4*4],    &fc1w[(n0+lrow)*ND + lc4*4]);
        cp16(&sm[0][0][lrow+64][lc4*4], &text[(m0+lrow+64)*ND + lc4*4]);
        cp16(&sm[0][1][lrow+64][lc4*4], &fc1w[(n0+lrow+64)*ND + lc4*4]);
        cp_commit();
    }
    for (int kt=0; kt<NKT; kt++){
        if (kt+1 < NKT){
            int k0 = (kt+1)*16, s = (kt+1)&1;
            cp16(&sm[s][0][lrow][lc4*4],    &text[(m0+lrow)*ND + k0 + lc4*4]);
            cp16(&sm[s][1][lrow][lc4*4],    &fc1w[(n0+lrow)*ND + k0 + lc4*4]);
            cp16(&sm[s][0][lrow+64][lc4*4], &text[(m0+lrow+64)*ND + k0 + lc4*4]);
            cp16(&sm[s][1][lrow+64][lc4*4], &fc1w[(n0+lrow+64)*ND + k0 + lc4*4]);
            cp_commit();
            cp_wait<1>();
        } else cp_wait<0>();
        __syncthreads();
        int s = kt & 1;
#pragma unroll
        for (int ks=0; ks<2; ks++){
            wmma::fragment<wmma::matrix_a,16,16,8,wmma::precision::tf32,wmma::row_major> af[2];
            wmma::fragment<wmma::matrix_b,16,16,8,wmma::precision::tf32,wmma::col_major> bf[4];
#pragma unroll
            for (int mf=0;mf<2;mf++)
                wmma::load_matrix_sync(af[mf], &sm[s][0][warp_m*32+mf*16][ks*8], 20);
#pragma unroll
            for (int nf=0;nf<4;nf++)
                wmma::load_matrix_sync(bf[nf], &sm[s][1][warp_n*64+nf*16][ks*8], 20);
#pragma unroll
            for (int mf=0;mf<2;mf++)
#pragma unroll
                for (int nf=0;nf<4;nf++)
                    wmma::mma_sync(acc[mf][nf], af[mf], bf[nf], acc[mf][nf]);
        }
        __syncthreads();
    }

    // fused epilogue: scale by ta[m], bias, relu, dot with fc2w over these 128 columns
    float* buf = &sm[0][0][0][0];   // need 64*132 = 8448 floats, have 10240
    int row = tid >> 2, q = tid & 3;
#pragma unroll
    for (int half=0; half<2; half++){
        if ((warp_m >> 1) == half){
            int rbase = (warp_m & 1)*32;
#pragma unroll
            for (int mf=0;mf<2;mf++)
#pragma unroll
                for (int nf=0;nf<4;nf++)
                    wmma::store_matrix_sync(&buf[(rbase+mf*16)*132 + warp_n*64+nf*16],
                                            acc[mf][nf], 132, wmma::mem_row_major);
        }
        __syncthreads();
        int gm = m0 + half*64 + row;
        float sc = g_ta[gm];
        float s = 0.f;
        int cbase = q*32;
#pragma unroll
        for (int c=0;c<32;c++){
            int gn = n0 + cbase + c;
            s += fmaxf(sc*buf[row*132 + cbase + c] + fc1b[gn], 0.f) * fc2w[gn];
        }
        s += __shfl_down_sync(0xffffffffu, s, 2);
        s += __shfl_down_sync(0xffffffffu, s, 1);
        if (q == 0) g_predpart[blockIdx.y*NM + gm] = s;
        __syncthreads();
    }
}

// ---------------- per-sample masked MSE from partials ----------------
__global__ void textloss_kernel(const float* __restrict__ sent, const int* __restrict__ lens,
                                const float* __restrict__ fc2b){
    __shared__ float sred[8];
    int b = blockIdx.x, tid = threadIdx.x;
    int len = lens[b];
    float s = 0.f;
    for (int t=tid; t<NT; t+=256){
        int m = b*NT + t;
        float p = fc2b[0];
#pragma unroll
        for (int pp=0; pp<NNB; pp++) p += g_predpart[pp*NM + m];
        if (sent[m] == 0.f) p = 0.f;
        if (t < len){
            float d = p - sent[m];
            s += d*d;
        }
    }
    s = wred(s);
    if ((tid & 31) == 0) sred[tid>>5] = s;
    __syncthreads();
    if (tid < 8){
        float v = sred[tid];
#pragma unroll
        for (int o=4;o;o>>=1) v += __shfl_xor_sync(0xffu, v, o);
        if (tid == 0) g_lossb[b] = v / (float)len;
    }
}

// ---------------- heads, contrast KL, semantic branch, outputs ----------------
__global__ __launch_bounds__(1024) void final_kernel(const float* __restrict__ fc2w,
                                                     const float* __restrict__ fc2b,
                                                     const float* __restrict__ fw,
                                                     const float* __restrict__ fb,
                                                     float* __restrict__ out){
    __shared__ float s_vs[32], s_ts[32], s_inv_nv[32], s_inv_nt[32];
    __shared__ float s_c[32][32], s_sim[32][32];
    __shared__ float s_crow[32], s_srow[32];
    __shared__ float s_var_v[ND], s_var_t[ND];
    __shared__ float s_red[32];
    __shared__ float s_tile[32][129];
    __shared__ float s_scal[2];

    int tid = threadIdx.x;
    int warp = tid >> 5, lane = tid & 31;

    {
        int b = warp;
        float vs=0.f, ts=0.f, nv=0.f, nt=0.f;
        for (int d=lane; d<ND; d+=32){
            float ve = g_vemb[b*ND+d], te = g_temb[b*ND+d], w = fc2w[d];
            vs += fmaxf(ve,0.f)*w; ts += te*w; nv += ve*ve; nt += te*te;
        }
        vs = wred(vs); ts = wred(ts); nv = wred(nv); nt = wred(nt);
        if (lane == 0){
            s_vs[b] = vs + fc2b[0];
            s_ts[b] = ts + fc2b[0];
            s_inv_nv[b] = 1.f/fmaxf(sqrtf(nv), 1e-12f);
            s_inv_nt[b] = 1.f/fmaxf(sqrtf(nt), 1e-12f);
        }
    }
    __syncthreads();

    int i = tid >> 5, j = tid & 31;
    float dot = 0.f;
    for (int kc=0; kc<ND; kc+=128){
        for (int e=tid; e<32*128; e+=1024){
            int r2 = e >> 7, c2 = e & 127;
            s_tile[r2][c2] = g_temb[r2*ND + kc + c2];
        }
        __syncthreads();
#pragma unroll 8
        for (int c=0;c<128;c++)
            dot += g_vemb[i*ND + kc + c] * s_tile[j][c];
        __syncthreads();
    }
    s_sim[i][j] = expf(dot * s_inv_nv[i] * s_inv_nt[j] * 5.0f);
    s_c[i][j]   = expf(-fabsf(s_vs[i] - s_ts[j]));
    __syncthreads();

    if (tid < 32){
        float cs=0.f, ss=0.f;
        for (int jj=0;jj<32;jj++){ cs += s_c[tid][jj]; ss += s_sim[tid][jj]; }
        s_crow[tid] = cs; s_srow[tid] = ss;
    }
    __syncthreads();

    {
        float cn = s_c[i][j]/s_crow[i];
        float sn = s_sim[i][j]/s_srow[i];
        float term = cn*(logf(cn) - logf(sn));
        term = wred(term);
        if (lane == 0) s_red[warp] = term;
        __syncthreads();
        if (tid < 32){
            float v = wred(s_red[tid]);
            if (tid == 0) out[32] = v * (1.f/32.f);
        }
    }
    __syncthreads();

    if (tid < ND){
        float sx=0.f, sx2=0.f;
        for (int b=0;b<32;b++){ float x = g_vcls[b*ND+tid]; sx += x; sx2 += x*x; }
        s_var_v[tid] = (sx2 - sx*sx*(1.f/32.f))*(1.f/31.f);
        sx=0.f; sx2=0.f;
        for (int b=0;b<32;b++){ float x = g_tcls[b*ND+tid]; sx += x; sx2 += x*x; }
        s_var_t[tid] = (sx2 - sx*sx*(1.f/32.f))*(1.f/31.f);
    }
    __syncthreads();
    {
        float v = (tid < ND) ? s_var_v[tid]*s_var_v[tid] : 0.f;
        v = wred(v);
        if (lane == 0) s_red[warp] = v;
        __syncthreads();
        if (tid < 32){
            float r = wred(s_red[tid]);
            if (tid == 0) s_scal[0] = 1.f/fmaxf(sqrtf(r), 1e-12f);
        }
        __syncthreads();
        float u = (tid < ND) ? s_var_t[tid]*s_var_t[tid] : 0.f;
        u = wred(u);
        if (lane == 0) s_red[warp] = u;
        __syncthreads();
        if (tid < 32){
            float r = wred(s_red[tid]);
            if (tid == 0) s_scal[1] = 1.f/fmaxf(sqrtf(r), 1e-12f);
        }
        __syncthreads();
        if (tid < ND){ s_var_v[tid] *= s_scal[0]; s_var_t[tid] *= s_scal[1]; }
    }
    __syncthreads();

    {
        int b = warp;
        float acc = 0.f;
        for (int d=lane; d<ND; d+=32){
            float sv  = g_vcls[b*ND+d]*(1.f + s_var_v[d]);
            float st2 = g_tcls[b*ND+d]*(1.f + s_var_t[d]);
            float fcls = 0.5f*(sv*st2 + g_vemb[b*ND+d]*g_temb[b*ND+d]);
            acc += fcls*fw[d];
        }
        acc = wred(acc);
        if (lane == 0)
            out[b] = acc + fb[0] + 0.1f*fabsf(s_ts[b] - s_vs[b]) - 0.5f;
    }

    if (tid < 32){
        float v = wred(g_lossb[tid]);
        if (tid == 0) out[33] = v * (1.f/32.f);
    }
}

// ---------------- launch ----------------
extern "C" void kernel_launch(void* const* d_in, const int* in_sizes, int n_in,
                              void* d_out, int out_size){
    const float* vision = (const float*)d_in[0];
    const float* text   = (const float*)d_in[1];
    const float* sent   = (const float*)d_in[2];
    const int*   lens   = (const int*)  d_in[3];
    const float* fc1_w  = (const float*)d_in[4];
    const float* fc1_b  = (const float*)d_in[5];
    const float* fc2_w  = (const float*)d_in[6];
    const float* fc2_b  = (const float*)d_in[7];
    const float* c1w    = (const float*)d_in[8];
    const float* c1b    = (const float*)d_in[9];
    const float* c2w    = (const float*)d_in[10];
    const float* c2b    = (const float*)d_in[11];
    const float* fw     = (const float*)d_in[12];
    const float* fb     = (const float*)d_in[13];
    float* out = (float*)d_out;

    prep_conv_kernel<<<1, 256>>>(c1w, c1b, c2w, c2b);
    gemm_amap_kernel<<<dim3(2,4,NB), 256>>>(vision, text);
    conv_fused_kernel<<<dim3(NCH,NB), 256>>>();
    ta_final_kernel<<<dim3(NB,2), 256>>>();
    cls_kernel<<<dim3(NB,3), 256>>>(vision, text);
    emb_kernel<<<dim3(NB,8), 256>>>(fc1_w, fc1_b);
    gemm_h_kernel<<<dim3(128,NNB), 256>>>(text, fc1_w, fc1_b, fc2_w);
    textloss_kernel<<<NB, 256>>>(sent, lens, fc2_b);
    final_kernel<<<1, 1024>>>(fc2_w, fc2_b, fw, fb, out);
}

// round 6
// speedup vs baseline: 3.1937x; 1.7630x over previous
#include <cuda_runtime.h>
#include <cuda_bf16.h>
#include <cstdint>
#include <mma.h>
using namespace nvcuda;

#define NB 32
#define NV 197
#define NVP 256          // padded amap row stride
#define NT 512
#define ND 768
#define NM (NB*NT)       // 16384
#define NNB 6            // n-blocks in gemm_h (768/128)
#define NCH 13           // conv row-chunks of 16

// ---------------- device scratch ----------------
static __device__ float g_amap[NB*NVP*NT];      // 16.8 MB
static __device__ float g_tapart[NCH*NB*NT];
static __device__ float g_ta[NM];
static __device__ float g_va[NB*NV];
static __device__ float g_vcls[NB*ND];
static __device__ float g_tcls[NB*ND];
static __device__ float g_temb[NB*ND];
static __device__ float g_vemb[NB*ND];
static __device__ float g_predpart[NNB*NM];
static __device__ float g_lossb[NB];
static __device__ float g_keff[9][25];
static __device__ float g_kbias[9];
static __device__ __nv_bfloat16 g_textbf[NM*ND];      // 25 MB
static __device__ __nv_bfloat16 g_visbf[NB*NV*ND];    // 9.7 MB
static __device__ __nv_bfloat16 g_w1bf[ND*ND];        // 1.2 MB

__device__ __forceinline__ float wred(float v){
#pragma unroll
    for (int o = 16; o; o >>= 1) v += __shfl_xor_sync(0xffffffffu, v, o);
    return v;
}
__device__ __forceinline__ float sigmoidf(float x){ return 1.f/(1.f + expf(-x)); }

// ---- cp.async helpers ----
__device__ __forceinline__ void cp16(void* s, const void* g){
    unsigned int sa = (unsigned int)__cvta_generic_to_shared(s);
    asm volatile("cp.async.cg.shared.global [%0], [%1], 16;" :: "r"(sa), "l"(g));
}
__device__ __forceinline__ void cp_commit(){ asm volatile("cp.async.commit_group;"); }
template<int N> __device__ __forceinline__ void cp_wait(){
    asm volatile("cp.async.wait_group %0;" :: "n"(N));
}

// ---------------- fp32 -> bf16 conversion pre-pass ----------------
#define CT1 (NM*ND/4)
#define CT2 (CT1 + NB*NV*ND/4)
#define CT3 (CT2 + ND*ND/4)
__global__ void convert_kernel(const float* __restrict__ text,
                               const float* __restrict__ vision,
                               const float* __restrict__ w1){
    int p = blockIdx.x*256 + threadIdx.x;    // float4 index; grid exact
    const float* src; __nv_bfloat16* dst; int off;
    if (p < CT1){ src = text; dst = g_textbf; off = p; }
    else if (p < CT2){ src = vision; dst = g_visbf; off = p - CT1; }
    else { src = w1; dst = g_w1bf; off = p - CT2; }
    float4 v = ((const float4*)src)[off];
    __nv_bfloat162* d2 = (__nv_bfloat162*)dst;
    d2[off*2]   = __floats2bfloat162_rn(v.x, v.y);
    d2[off*2+1] = __floats2bfloat162_rn(v.z, v.w);
}

// ---------------- compose conv2(conv1(.)) into 9 border-variant 5x5 kernels ----------------
__global__ void prep_conv_kernel(const float* __restrict__ w1, const float* __restrict__ b1,
                                 const float* __restrict__ w2, const float* __restrict__ b2){
    int tid = threadIdx.x;
    if (tid < 225){
        int var = tid/25, uv = tid%25, u = uv/5, v = uv%5;
        int ri = var/3, rj = var%3;
        float s = 0.f;
        for (int d1=0; d1<3; d1++){
            if ((ri==0 && d1==0) || (ri==2 && d1==2)) continue;
            int d2 = u - d1; if (d2 < 0 || d2 > 2) continue;
            for (int e1=0; e1<3; e1++){
                if ((rj==0 && e1==0) || (rj==2 && e1==2)) continue;
                int e2 = v - e1; if (e2 < 0 || e2 > 2) continue;
                for (int c=0; c<64; c++)
                    s += w2[c*9 + d1*3 + e1] * w1[c*9 + d2*3 + e2];
            }
        }
        g_keff[var][uv] = s;
    } else if (tid < 234){
        int var = tid - 225;
        int ri = var/3, rj = var%3;
        float s = b2[0];
        for (int c=0; c<64; c++){
            float t = 0.f;
            for (int d1=0; d1<3; d1++){
                if ((ri==0 && d1==0) || (ri==2 && d1==2)) continue;
                for (int e1=0; e1<3; e1++){
                    if ((rj==0 && e1==0) || (rj==2 && e1==2)) continue;
                    t += w2[c*9 + d1*3 + e1];
                }
            }
            s += b1[c]*t;
        }
        g_kbias[var] = s;
    }
}

// ============ bf16 GEMM 1 (cp.async 2-stage, BK=32): amap = vision . text^T ============
__global__ __launch_bounds__(256,2) void gemm_amap_kernel(){
    __shared__ __align__(16) __nv_bfloat16 sm[2][2][128][40];  // 40 KB
    int b  = blockIdx.z;
    const __nv_bfloat16* A  = g_visbf  + (size_t)b*NV*ND;
    const __nv_bfloat16* Bp = g_textbf + (size_t)b*NT*ND;
    int m0 = blockIdx.x*128, n0 = blockIdx.y*128;
    int tid = threadIdx.x, wid = tid >> 5;
    int warp_m = wid >> 1, warp_n = wid & 1;

    wmma::fragment<wmma::accumulator,16,16,16,float> acc[2][4];
#pragma unroll
    for (int mf=0;mf<2;mf++)
#pragma unroll
        for (int nf=0;nf<4;nf++) wmma::fill_fragment(acc[mf][nf], 0.f);

    const int NKT = ND/32;   // 24
    // load helper inline (stage s, k-offset k0)
#define AMAP_LOAD(s, k0)  do {                                              \
    _Pragma("unroll")                                                       \
    for (int l=0; l<2; l++){                                                \
        int idx = tid + l*256;                                              \
        int r = idx >> 2, c8 = idx & 3;                                     \
        int gm = m0 + r; if (gm > NV-1) gm = NV-1;                          \
        cp16(&sm[s][0][r][c8*8], &A [(size_t)gm*ND + (k0) + c8*8]);         \
        cp16(&sm[s][1][r][c8*8], &Bp[(size_t)(n0+r)*ND + (k0) + c8*8]);     \
    } } while(0)

    AMAP_LOAD(0, 0);
    cp_commit();
    for (int kt=0; kt<NKT; kt++){
        if (kt+1 < NKT){
            AMAP_LOAD((kt+1)&1, (kt+1)*32);
            cp_commit();
            cp_wait<1>();
        } else cp_wait<0>();
        __syncthreads();
        int s = kt & 1;
#pragma unroll
        for (int ks=0; ks<2; ks++){
            wmma::fragment<wmma::matrix_a,16,16,16,__nv_bfloat16,wmma::row_major> af[2];
            wmma::fragment<wmma::matrix_b,16,16,16,__nv_bfloat16,wmma::col_major> bf[4];
#pragma unroll
            for (int mf=0;mf<2;mf++)
                wmma::load_matrix_sync(af[mf], &sm[s][0][warp_m*32+mf*16][ks*16], 40);
#pragma unroll
            for (int nf=0;nf<4;nf++)
                wmma::load_matrix_sync(bf[nf], &sm[s][1][warp_n*64+nf*16][ks*16], 40);
#pragma unroll
            for (int mf=0;mf<2;mf++)
#pragma unroll
                for (int nf=0;nf<4;nf++)
                    wmma::mma_sync(acc[mf][nf], af[mf], bf[nf], acc[mf][nf]);
        }
        __syncthreads();
    }
#undef AMAP_LOAD
    float* C = g_amap + (size_t)b*NVP*NT;
#pragma unroll
    for (int mf=0;mf<2;mf++)
#pragma unroll
        for (int nf=0;nf<4;nf++)
            wmma::store_matrix_sync(&C[(size_t)(m0+warp_m*32+mf*16)*NT + n0+warp_n*64+nf*16],
                                    acc[mf][nf], NT, wmma::mem_row_major);
}

// ============ fused 5x5 conv + relu + row-sums (va) + column partials (ta) ============
__global__ __launch_bounds__(256) void conv_fused_kernel(){
    __shared__ float smz[20][NT];
    __shared__ float kv[9][25];
    __shared__ float kb[9];
    __shared__ float rowred[16][8];
    int c = blockIdx.x;
    int b = blockIdx.y;
    int tid = threadIdx.x;
    int warp = tid >> 5, lane = tid & 31;
    if (tid < 225) ((float*)kv)[tid] = ((const float*)g_keff)[tid];
    else if (tid >= 240 && tid < 249) kb[tid-240] = g_kbias[tid-240];

    int i0 = c*16;
    const float* base = g_amap + (size_t)b*NVP*NT;
#pragma unroll
    for (int l=0; l<10; l++){
        int e = tid + l*256;
        int rr = e >> 7, c4 = e & 127;
        int gi = i0 - 2 + rr;
        float4 v = make_float4(0.f,0.f,0.f,0.f);
        if (gi >= 0 && gi < NV) v = *(const float4*)&base[(size_t)gi*NT + c4*4];
        *(float4*)&smz[rr][c4*4] = v;
    }
    __syncthreads();

    float colsum0 = 0.f, colsum1 = 0.f;
    float rowpart[16];
#pragma unroll
    for (int rr=0; rr<16; rr++){
        int i = i0 + rr;
        float rs = 0.f;
        if (i < NV){
            int ri = (i==0) ? 0 : ((i==NV-1) ? 2 : 1);
#pragma unroll
            for (int jj=0; jj<2; jj++){
                int j = tid + jj*256;
                int rj = (j==0) ? 0 : ((j==NT-1) ? 2 : 1);
                int var = ri*3 + rj;
                float s = kb[var];
                const float* kp = kv[var];
#pragma unroll
                for (int u=0; u<5; u++){
#pragma unroll
                    for (int v=0; v<5; v++){
                        int j2 = j + v - 2;
                        if (j2 >= 0 && j2 < NT)
                            s += kp[u*5+v] * smz[rr+u][j2];
                    }
                }
                s = fmaxf(s, 0.f);
                if (jj == 0) colsum0 += s; else colsum1 += s;
                rs += s;
            }
        }
        rowpart[rr] = rs;
    }
    float* tp = g_tapart + (size_t)(c*NB + b)*NT;
    tp[tid]       = colsum0;
    tp[tid + 256] = colsum1;
#pragma unroll
    for (int rr=0; rr<16; rr++){
        float v = wred(rowpart[rr]);
        if (lane == 0) rowred[rr][warp] = v;
    }
    __syncthreads();
    if (tid < 128){
        int rr = tid >> 3, slot = tid & 7;
        float v = rowred[rr][slot];
        v += __shfl_down_sync(0xffffffffu, v, 4, 8);
        v += __shfl_down_sync(0xffffffffu, v, 2, 8);
        v += __shfl_down_sync(0xffffffffu, v, 1, 8);
        if (slot == 0){
            int gi = i0 + rr;
            if (gi < NV) g_va[b*NV + gi] = sigmoidf(v * (1.f/(float)NT));
        }
    }
}

// ---------------- ta finalize ----------------
__global__ void ta_final_kernel(){
    int b = blockIdx.x;
    int t = blockIdx.y*256 + threadIdx.x;
    float s = 0.f;
#pragma unroll
    for (int c=0; c<NCH; c++) s += g_tapart[(size_t)(c*NB + b)*NT + t];
    g_ta[b*NT + t] = sigmoidf(s * (1.f/(float)NV));
}

// ============ bf16 GEMM 2 (cp.async 2-stage, BK=32) + fused pred epilogue ============
__global__ __launch_bounds__(256,2) void gemm_h_kernel(const float* __restrict__ fc1b,
                                                       const float* __restrict__ fc2w){
    __shared__ __align__(16) __nv_bfloat16 sm[2][2][128][40];  // 40 KB
    int m0 = blockIdx.x*128, n0 = blockIdx.y*128;
    int tid = threadIdx.x, wid = tid >> 5;
    int warp_m = wid >> 1, warp_n = wid & 1;

    wmma::fragment<wmma::accumulator,16,16,16,float> acc[2][4];
#pragma unroll
    for (int mf=0;mf<2;mf++)
#pragma unroll
        for (int nf=0;nf<4;nf++) wmma::fill_fragment(acc[mf][nf], 0.f);

    const int NKT = ND/32;
#define H_LOAD(s, k0)  do {                                                    \
    _Pragma("unroll")                                                          \
    for (int l=0; l<2; l++){                                                   \
        int idx = tid + l*256;                                                 \
        int r = idx >> 2, c8 = idx & 3;                                        \
        cp16(&sm[s][0][r][c8*8], &g_textbf[(size_t)(m0+r)*ND + (k0) + c8*8]);  \
        cp16(&sm[s][1][r][c8*8], &g_w1bf  [(size_t)(n0+r)*ND + (k0) + c8*8]);  \
    } } while(0)

    H_LOAD(0, 0);
    cp_commit();
    for (int kt=0; kt<NKT; kt++){
        if (kt+1 < NKT){
            H_LOAD((kt+1)&1, (kt+1)*32);
            cp_commit();
            cp_wait<1>();
        } else cp_wait<0>();
        __syncthreads();
        int s = kt & 1;
#pragma unroll
        for (int ks=0; ks<2; ks++){
            wmma::fragment<wmma::matrix_a,16,16,16,__nv_bfloat16,wmma::row_major> af[2];
            wmma::fragment<wmma::matrix_b,16,16,16,__nv_bfloat16,wmma::col_major> bf[4];
#pragma unroll
            for (int mf=0;mf<2;mf++)
                wmma::load_matrix_sync(af[mf], &sm[s][0][warp_m*32+mf*16][ks*16], 40);
#pragma unroll
            for (int nf=0;nf<4;nf++)
                wmma::load_matrix_sync(bf[nf], &sm[s][1][warp_n*64+nf*16][ks*16], 40);
#pragma unroll
            for (int mf=0;mf<2;mf++)
#pragma unroll
                for (int nf=0;nf<4;nf++)
                    wmma::mma_sync(acc[mf][nf], af[mf], bf[nf], acc[mf][nf]);
        }
        __syncthreads();
    }
#undef H_LOAD

    // fused epilogue: scale by ta[m], bias, relu, dot with fc2w
    float* buf = (float*)sm;    // need 64*132*4 = 33.8KB <= 40KB
    int row = tid >> 2, q = tid & 3;
#pragma unroll
    for (int half=0; half<2; half++){
        if ((warp_m >> 1) == half){
            int rbase = (warp_m & 1)*32;
#pragma unroll
            for (int mf=0;mf<2;mf++)
#pragma unroll
                for (int nf=0;nf<4;nf++)
                    wmma::store_matrix_sync(&buf[(rbase+mf*16)*132 + warp_n*64+nf*16],
                                            acc[mf][nf], 132, wmma::mem_row_major);
        }
        __syncthreads();
        int gm = m0 + half*64 + row;
        float sc = g_ta[gm];
        float s = 0.f;
        int cbase = q*32;
#pragma unroll
        for (int c=0;c<32;c++){
            int gn = n0 + cbase + c;
            s += fmaxf(sc*buf[row*132 + cbase + c] + fc1b[gn], 0.f) * fc2w[gn];
        }
        s += __shfl_down_sync(0xffffffffu, s, 2);
        s += __shfl_down_sync(0xffffffffu, s, 1);
        if (q == 0) g_predpart[blockIdx.y*NM + gm] = s;
        __syncthreads();
    }
}

// ---------------- vision_CLS / text_CLS : grid (NB,3)  (fp32 inputs, precision-sensitive path) ----------------
__global__ void cls_kernel(const float* __restrict__ vision, const float* __restrict__ text){
    int b = blockIdx.x;
    int d = blockIdx.y*256 + threadIdx.x;
    float av = 0.f, at = 0.f;
    const float* vb = vision + (size_t)b*NV*ND + d;
#pragma unroll 4
    for (int v=0; v<NV; v++) av += g_va[b*NV+v] * vb[(size_t)v*ND];
    const float* tb = text + (size_t)b*NT*ND + d;
#pragma unroll 4
    for (int t=0; t<NT; t++) at += g_ta[b*NT+t] * tb[(size_t)t*ND];
    g_vcls[b*ND+d] = av * (1.f/(float)NV);
    g_tcls[b*ND+d] = at * (1.f/(float)NT);
}

// ---------------- v_emb/t_emb = fc1(CLS)  (fp32, grid (NB,8)) ----------------
__global__ void emb_kernel(const float* __restrict__ fc1w, const float* __restrict__ fc1b){
    __shared__ float sv[ND], st[ND];
    int b = blockIdx.x, tid = threadIdx.x;
    int warp = tid >> 5, lane = tid & 31;
    for (int d=tid; d<ND; d+=256){ sv[d] = g_vcls[b*ND+d]; st[d] = g_tcls[b*ND+d]; }
    __syncthreads();
    int n0 = blockIdx.y*96 + warp*12;
#pragma unroll
    for (int k=0; k<12; k++){
        int n = n0 + k;
        const float* wr = fc1w + (size_t)n*ND;
        float a=0.f, cc=0.f;
        for (int d=lane; d<ND; d+=32){ float w = wr[d]; a += w*sv[d]; cc += w*st[d]; }
        a = wred(a); cc = wred(cc);
        if (lane == 0){
            g_vemb[b*ND+n] = a + fc1b[n];
            g_temb[b*ND+n] = cc + fc1b[n];
        }
    }
}

// ---------------- per-sample masked MSE from partials ----------------
__global__ void textloss_kernel(const float* __restrict__ sent, const int* __restrict__ lens,
                                const float* __restrict__ fc2b){
    __shared__ float sred[8];
    int b = blockIdx.x, tid = threadIdx.x;
    int len = lens[b];
    float s = 0.f;
    for (int t=tid; t<NT; t+=256){
        int m = b*NT + t;
        float p = fc2b[0];
#pragma unroll
        for (int pp=0; pp<NNB; pp++) p += g_predpart[pp*NM + m];
        if (sent[m] == 0.f) p = 0.f;
        if (t < len){
            float d = p - sent[m];
            s += d*d;
        }
    }
    s = wred(s);
    if ((tid & 31) == 0) sred[tid>>5] = s;
    __syncthreads();
    if (tid < 8){
        float v = sred[tid];
#pragma unroll
        for (int o=4;o;o>>=1) v += __shfl_xor_sync(0xffu, v, o);
        if (tid == 0) g_lossb[b] = v / (float)len;
    }
}

// ---------------- heads, contrast KL, semantic branch, outputs ----------------
__global__ __launch_bounds__(1024) void final_kernel(const float* __restrict__ fc2w,
                                                     const float* __restrict__ fc2b,
                                                     const float* __restrict__ fw,
                                                     const float* __restrict__ fb,
                                                     float* __restrict__ out){
    __shared__ float s_vs[32], s_ts[32], s_inv_nv[32], s_inv_nt[32];
    __shared__ float s_c[32][32], s_sim[32][32];
    __shared__ float s_crow[32], s_srow[32];
    __shared__ float s_var_v[ND], s_var_t[ND];
    __shared__ float s_red[32];
    __shared__ float s_tile[32][129];
    __shared__ float s_scal[2];

    int tid = threadIdx.x;
    int warp = tid >> 5, lane = tid & 31;

    {
        int b = warp;
        float vs=0.f, ts=0.f, nv=0.f, nt=0.f;
        for (int d=lane; d<ND; d+=32){
            float ve = g_vemb[b*ND+d], te = g_temb[b*ND+d], w = fc2w[d];
            vs += fmaxf(ve,0.f)*w; ts += te*w; nv += ve*ve; nt += te*te;
        }
        vs = wred(vs); ts = wred(ts); nv = wred(nv); nt = wred(nt);
        if (lane == 0){
            s_vs[b] = vs + fc2b[0];
            s_ts[b] = ts + fc2b[0];
            s_inv_nv[b] = 1.f/fmaxf(sqrtf(nv), 1e-12f);
            s_inv_nt[b] = 1.f/fmaxf(sqrtf(nt), 1e-12f);
        }
    }
    __syncthreads();

    int i = tid >> 5, j = tid & 31;
    float dot = 0.f;
    for (int kc=0; kc<ND; kc+=128){
        for (int e=tid; e<32*128; e+=1024){
            int r2 = e >> 7, c2 = e & 127;
            s_tile[r2][c2] = g_temb[r2*ND + kc + c2];
        }
        __syncthreads();
#pragma unroll 8
        for (int c=0;c<128;c++)
            dot += g_vemb[i*ND + kc + c] * s_tile[j][c];
        __syncthreads();
    }
    s_sim[i][j] = expf(dot * s_inv_nv[i] * s_inv_nt[j] * 5.0f);
    s_c[i][j]   = expf(-fabsf(s_vs[i] - s_ts[j]));
    __syncthreads();

    if (tid < 32){
        float cs=0.f, ss=0.f;
        for (int jj=0;jj<32;jj++){ cs += s_c[tid][jj]; ss += s_sim[tid][jj]; }
        s_crow[tid] = cs; s_srow[tid] = ss;
    }
    __syncthreads();

    {
        float cn = s_c[i][j]/s_crow[i];
        float sn = s_sim[i][j]/s_srow[i];
        float term = cn*(logf(cn) - logf(sn));
        term = wred(term);
        if (lane == 0) s_red[warp] = term;
        __syncthreads();
        if (tid < 32){
            float v = wred(s_red[tid]);
            if (tid == 0) out[32] = v * (1.f/32.f);
        }
    }
    __syncthreads();

    if (tid < ND){
        float sx=0.f, sx2=0.f;
        for (int b=0;b<32;b++){ float x = g_vcls[b*ND+tid]; sx += x; sx2 += x*x; }
        s_var_v[tid] = (sx2 - sx*sx*(1.f/32.f))*(1.f/31.f);
        sx=0.f; sx2=0.f;
        for (int b=0;b<32;b++){ float x = g_tcls[b*ND+tid]; sx += x; sx2 += x*x; }
        s_var_t[tid] = (sx2 - sx*sx*(1.f/32.f))*(1.f/31.f);
    }
    __syncthreads();
    {
        float v = (tid < ND) ? s_var_v[tid]*s_var_v[tid] : 0.f;
        v = wred(v);
        if (lane == 0) s_red[warp] = v;
        __syncthreads();
        if (tid < 32){
            float r = wred(s_red[tid]);
            if (tid == 0) s_scal[0] = 1.f/fmaxf(sqrtf(r), 1e-12f);
        }
        __syncthreads();
        float u = (tid < ND) ? s_var_t[tid]*s_var_t[tid] : 0.f;
        u = wred(u);
        if (lane == 0) s_red[warp] = u;
        __syncthreads();
        if (tid < 32){
            float r = wred(s_red[tid]);
            if (tid == 0) s_scal[1] = 1.f/fmaxf(sqrtf(r), 1e-12f);
        }
        __syncthreads();
        if (tid < ND){ s_var_v[tid] *= s_scal[0]; s_var_t[tid] *= s_scal[1]; }
    }
    __syncthreads();

    {
        int b = warp;
        float acc = 0.f;
        for (int d=lane; d<ND; d+=32){
            float sv  = g_vcls[b*ND+d]*(1.f + s_var_v[d]);
            float st2 = g_tcls[b*ND+d]*(1.f + s_var_t[d]);
            float fcls = 0.5f*(sv*st2 + g_vemb[b*ND+d]*g_temb[b*ND+d]);
            acc += fcls*fw[d];
        }
        acc = wred(acc);
        if (lane == 0)
            out[b] = acc + fb[0] + 0.1f*fabsf(s_ts[b] - s_vs[b]) - 0.5f;
    }

    if (tid < 32){
        float v = wred(g_lossb[tid]);
        if (tid == 0) out[33] = v * (1.f/32.f);
    }
}

// ---------------- launch ----------------
extern "C" void kernel_launch(void* const* d_in, const int* in_sizes, int n_in,
                              void* d_out, int out_size){
    const float* vision = (const float*)d_in[0];
    const float* text   = (const float*)d_in[1];
    const float* sent   = (const float*)d_in[2];
    const int*   lens   = (const int*)  d_in[3];
    const float* fc1_w  = (const float*)d_in[4];
    const float* fc1_b  = (const float*)d_in[5];
    const float* fc2_w  = (const float*)d_in[6];
    const float* fc2_b  = (const float*)d_in[7];
    const float* c1w    = (const float*)d_in[8];
    const float* c1b    = (const float*)d_in[9];
    const float* c2w    = (const float*)d_in[10];
    const float* c2b    = (const float*)d_in[11];
    const float* fw     = (const float*)d_in[12];
    const float* fb     = (const float*)d_in[13];
    float* out = (float*)d_out;

    prep_conv_kernel<<<1, 256>>>(c1w, c1b, c2w, c2b);
    convert_kernel<<<CT3/256, 256>>>(text, vision, fc1_w);
    gemm_amap_kernel<<<dim3(2,4,NB), 256>>>();
    conv_fused_kernel<<<dim3(NCH,NB), 256>>>();
    ta_final_kernel<<<dim3(NB,2), 256>>>();
    gemm_h_kernel<<<dim3(128,NNB), 256>>>(fc1_b, fc2_w);
    cls_kernel<<<dim3(NB,3), 256>>>(vision, text);
    emb_kernel<<<dim3(NB,8), 256>>>(fc1_w, fc1_b);
    textloss_kernel<<<NB, 256>>>(sent, lens, fc2_b);
    final_kernel<<<1, 1024>>>(fc2_w, fc2_b, fw, fb, out);
}

// round 7
// speedup vs baseline: 3.3383x; 1.0453x over previous
#include <cuda_runtime.h>
#include <cuda_bf16.h>
#include <cstdint>
#include <mma.h>
using namespace nvcuda;

#define NB 32
#define NV 197
#define NVP 256          // padded amap row stride
#define NT 512
#define ND 768
#define NM (NB*NT)       // 16384
#define NNB 6            // n-blocks in gemm_h (768/128)
#define NCH 13           // conv row-chunks of 16

// ---------------- device scratch ----------------
static __device__ float g_amap[NB*NVP*NT];      // 16.8 MB
static __device__ float g_tapart[NCH*NB*NT];
static __device__ float g_ta[NM];
static __device__ float g_va[NB*NV];
static __device__ float g_vcls[NB*ND];
static __device__ float g_tcls[NB*ND];
static __device__ float g_temb[NB*ND];
static __device__ float g_vemb[NB*ND];
static __device__ float g_predpart[NNB*NM];
static __device__ float g_lossb[NB];
static __device__ float g_keff[9][25];
static __device__ float g_kbias[9];
static __device__ __nv_bfloat16 g_textbf[NM*ND];      // 25 MB
static __device__ __nv_bfloat16 g_visbf[NB*NV*ND];    // 9.7 MB
static __device__ __nv_bfloat16 g_w1bf[ND*ND];        // 1.2 MB

__device__ __forceinline__ float wred(float v){
#pragma unroll
    for (int o = 16; o; o >>= 1) v += __shfl_xor_sync(0xffffffffu, v, o);
    return v;
}
__device__ __forceinline__ float sigmoidf(float x){ return 1.f/(1.f + expf(-x)); }

// ---- cp.async helpers ----
__device__ __forceinline__ void cp16(void* s, const void* g){
    unsigned int sa = (unsigned int)__cvta_generic_to_shared(s);
    asm volatile("cp.async.cg.shared.global [%0], [%1], 16;" :: "r"(sa), "l"(g));
}
__device__ __forceinline__ void cp_commit(){ asm volatile("cp.async.commit_group;"); }
template<int N> __device__ __forceinline__ void cp_wait(){
    asm volatile("cp.async.wait_group %0;" :: "n"(N));
}

// ---------------- fp32 -> bf16 conversion + conv composition (merged) ----------------
#define CT1 (NM*ND/4)
#define CT2 (CT1 + NB*NV*ND/4)
#define CT3 (CT2 + ND*ND/4)
#define NCVT (CT3/256)
__global__ void convert_prep_kernel(const float* __restrict__ text,
                                    const float* __restrict__ vision,
                                    const float* __restrict__ fc1w,
                                    const float* __restrict__ w1, const float* __restrict__ b1,
                                    const float* __restrict__ w2, const float* __restrict__ b2){
    if (blockIdx.x < NCVT){
        int p = blockIdx.x*256 + threadIdx.x;
        const float* src; __nv_bfloat16* dst; int off;
        if (p < CT1){ src = text; dst = g_textbf; off = p; }
        else if (p < CT2){ src = vision; dst = g_visbf; off = p - CT1; }
        else { src = fc1w; dst = g_w1bf; off = p - CT2; }
        float4 v = ((const float4*)src)[off];
        __nv_bfloat162* d2 = (__nv_bfloat162*)dst;
        d2[off*2]   = __floats2bfloat162_rn(v.x, v.y);
        d2[off*2+1] = __floats2bfloat162_rn(v.z, v.w);
        return;
    }
    // last block: compose conv2(conv1(.)) into 9 border-variant 5x5 kernels
    int tid = threadIdx.x;
    if (tid < 225){
        int var = tid/25, uv = tid%25, u = uv/5, v = uv%5;
        int ri = var/3, rj = var%3;
        float s = 0.f;
        for (int d1=0; d1<3; d1++){
            if ((ri==0 && d1==0) || (ri==2 && d1==2)) continue;
            int d2 = u - d1; if (d2 < 0 || d2 > 2) continue;
            for (int e1=0; e1<3; e1++){
                if ((rj==0 && e1==0) || (rj==2 && e1==2)) continue;
                int e2 = v - e1; if (e2 < 0 || e2 > 2) continue;
                for (int c=0; c<64; c++)
                    s += w2[c*9 + d1*3 + e1] * w1[c*9 + d2*3 + e2];
            }
        }
        g_keff[var][uv] = s;
    } else if (tid < 234){
        int var = tid - 225;
        int ri = var/3, rj = var%3;
        float s = b2[0];
        for (int c=0; c<64; c++){
            float t = 0.f;
            for (int d1=0; d1<3; d1++){
                if ((ri==0 && d1==0) || (ri==2 && d1==2)) continue;
                for (int e1=0; e1<3; e1++){
                    if ((rj==0 && e1==0) || (rj==2 && e1==2)) continue;
                    t += w2[c*9 + d1*3 + e1];
                }
            }
            s += b1[c]*t;
        }
        g_kbias[var] = s;
    }
}

// ============ bf16 GEMM 1 (cp.async 2-stage, single-sync): amap = vision . text^T ============
__global__ __launch_bounds__(256,2) void gemm_amap_kernel(){
    __shared__ __align__(16) __nv_bfloat16 sm[2][2][128][40];  // 40 KB
    int b  = blockIdx.z;
    const __nv_bfloat16* A  = g_visbf  + (size_t)b*NV*ND;
    const __nv_bfloat16* Bp = g_textbf + (size_t)b*NT*ND;
    int m0 = blockIdx.x*128, n0 = blockIdx.y*128;
    int tid = threadIdx.x, wid = tid >> 5;
    int warp_m = wid >> 1, warp_n = wid & 1;

    wmma::fragment<wmma::accumulator,16,16,16,float> acc[2][4];
#pragma unroll
    for (int mf=0;mf<2;mf++)
#pragma unroll
        for (int nf=0;nf<4;nf++) wmma::fill_fragment(acc[mf][nf], 0.f);

    const int NKT = ND/32;   // 24
#define AMAP_LOAD(s, k0)  do {                                              \
    _Pragma("unroll")                                                       \
    for (int l=0; l<2; l++){                                                \
        int idx = tid + l*256;                                              \
        int r = idx >> 2, c8 = idx & 3;                                     \
        int gm = m0 + r; if (gm > NV-1) gm = NV-1;                          \
        cp16(&sm[s][0][r][c8*8], &A [(size_t)gm*ND + (k0) + c8*8]);         \
        cp16(&sm[s][1][r][c8*8], &Bp[(size_t)(n0+r)*ND + (k0) + c8*8]);     \
    } } while(0)

    AMAP_LOAD(0, 0);
    cp_commit();
    for (int kt=0; kt<NKT; kt++){
        cp_wait<0>();
        __syncthreads();                       // tile kt visible; compute kt-1 done everywhere
        if (kt+1 < NKT){ AMAP_LOAD((kt+1)&1, (kt+1)*32); cp_commit(); }
        int s = kt & 1;
#pragma unroll
        for (int ks=0; ks<2; ks++){
            wmma::fragment<wmma::matrix_a,16,16,16,__nv_bfloat16,wmma::row_major> af[2];
            wmma::fragment<wmma::matrix_b,16,16,16,__nv_bfloat16,wmma::col_major> bf[4];
#pragma unroll
            for (int mf=0;mf<2;mf++)
                wmma::load_matrix_sync(af[mf], &sm[s][0][warp_m*32+mf*16][ks*16], 40);
#pragma unroll
            for (int nf=0;nf<4;nf++)
                wmma::load_matrix_sync(bf[nf], &sm[s][1][warp_n*64+nf*16][ks*16], 40);
#pragma unroll
            for (int mf=0;mf<2;mf++)
#pragma unroll
                for (int nf=0;nf<4;nf++)
                    wmma::mma_sync(acc[mf][nf], af[mf], bf[nf], acc[mf][nf]);
        }
    }
#undef AMAP_LOAD
    float* C = g_amap + (size_t)b*NVP*NT;
#pragma unroll
    for (int mf=0;mf<2;mf++)
#pragma unroll
        for (int nf=0;nf<4;nf++)
            wmma::store_matrix_sync(&C[(size_t)(m0+warp_m*32+mf*16)*NT + n0+warp_n*64+nf*16],
                                    acc[mf][nf], NT, wmma::mem_row_major);
}

// ============ fused 5x5 conv + relu + row-sums (va) + column partials (ta) ============
// register-window stencil: 5 LDS per interior output row instead of 25
__global__ __launch_bounds__(256) void conv_fused_kernel(){
    __shared__ float smz[20][NT];
    __shared__ float kvs[9][25];
    __shared__ float kbs[9];
    __shared__ float rowred[16][8];
    int c = blockIdx.x;
    int b = blockIdx.y;
    int tid = threadIdx.x;
    int warp = tid >> 5, lane = tid & 31;
    if (tid < 225) ((float*)kvs)[tid] = ((const float*)g_keff)[tid];
    else if (tid >= 240 && tid < 249) kbs[tid-240] = g_kbias[tid-240];

    int i0 = c*16;
    const float* base = g_amap + (size_t)b*NVP*NT;
#pragma unroll
    for (int l=0; l<10; l++){
        int e = tid + l*256;
        int rr = e >> 7, c4 = e & 127;
        int gi = i0 - 2 + rr;
        float4 v = make_float4(0.f,0.f,0.f,0.f);
        if (gi >= 0 && gi < NV) v = *(const float4*)&base[(size_t)gi*NT + c4*4];
        *(float4*)&smz[rr][c4*4] = v;
    }
    __syncthreads();

    float rowpart[16];
#pragma unroll
    for (int rr=0;rr<16;rr++) rowpart[rr] = 0.f;

#pragma unroll
    for (int jj=0; jj<2; jj++){
        int j = tid + jj*256;
        int rj = (j==0) ? 0 : ((j==NT-1) ? 2 : 1);
        // interior kernel (ri=1) in registers
        float kreg[25];
#pragma unroll
        for (int t=0;t<25;t++) kreg[t] = kvs[3+rj][t];
        float kbmid = kbs[3+rj];

        float w[5][5];
#pragma unroll
        for (int u=0;u<4;u++)
#pragma unroll
            for (int v=0;v<5;v++){
                int j2 = j + v - 2;
                w[u][v] = (j2>=0 && j2<NT) ? smz[u][j2] : 0.f;
            }
        float colsum = 0.f;
#pragma unroll
        for (int rr=0; rr<16; rr++){
#pragma unroll
            for (int v=0;v<5;v++){
                int j2 = j + v - 2;
                w[4][v] = (j2>=0 && j2<NT) ? smz[rr+4][j2] : 0.f;
            }
            int i = i0 + rr;
            if (i < NV){
                float s;
                if (i==0 || i==NV-1){           // rare border rows: smem kernel
                    int var = ((i==0)?0:6) + rj;
                    s = kbs[var];
                    const float* kp = kvs[var];
#pragma unroll
                    for (int u=0;u<5;u++)
#pragma unroll
                        for (int v=0;v<5;v++) s += kp[u*5+v]*w[u][v];
                } else {
                    s = kbmid;
#pragma unroll
                    for (int u=0;u<5;u++)
#pragma unroll
                        for (int v=0;v<5;v++) s += kreg[u*5+v]*w[u][v];
                }
                s = fmaxf(s, 0.f);
                colsum += s;
                rowpart[rr] += s;
            }
            // shift window up
#pragma unroll
            for (int u=0;u<4;u++)
#pragma unroll
                for (int v=0;v<5;v++) w[u][v] = w[u+1][v];
        }
        g_tapart[(size_t)(c*NB + b)*NT + j] = colsum;
    }
    // row sums -> va
#pragma unroll
    for (int rr=0; rr<16; rr++){
        float v = wred(rowpart[rr]);
        if (lane == 0) rowred[rr][warp] = v;
    }
    __syncthreads();
    if (tid < 128){
        int rr = tid >> 3, slot = tid & 7;
        float v = rowred[rr][slot];
        v += __shfl_down_sync(0xffffffffu, v, 4, 8);
        v += __shfl_down_sync(0xffffffffu, v, 2, 8);
        v += __shfl_down_sync(0xffffffffu, v, 1, 8);
        if (slot == 0){
            int gi = i0 + rr;
            if (gi < NV) g_va[b*NV + gi] = sigmoidf(v * (1.f/(float)NT));
        }
    }
}

// ============ bf16 GEMM 2 (single-sync 2-stage) + inline ta + fused pred epilogue ============
__global__ __launch_bounds__(256,2) void gemm_h_kernel(const float* __restrict__ fc1b,
                                                       const float* __restrict__ fc2w){
    __shared__ __align__(16) __nv_bfloat16 sm[2][2][128][40];  // 40 KB
    __shared__ float sta[128];
    int m0 = blockIdx.x*128, n0 = blockIdx.y*128;
    int tid = threadIdx.x, wid = tid >> 5;
    int warp_m = wid >> 1, warp_n = wid & 1;

    // inline ta for this block's 128 rows (from conv column partials)
    {
        int bb = m0 / NT, t0 = m0 % NT;
        if (tid < 128){
            float s = 0.f;
#pragma unroll
            for (int c=0;c<NCH;c++) s += g_tapart[(size_t)(c*NB + bb)*NT + t0 + tid];
            float v = sigmoidf(s * (1.f/(float)NV));
            sta[tid] = v;
            if (blockIdx.y == 0) g_ta[m0 + tid] = v;
        }
    }

    wmma::fragment<wmma::accumulator,16,16,16,float> acc[2][4];
#pragma unroll
    for (int mf=0;mf<2;mf++)
#pragma unroll
        for (int nf=0;nf<4;nf++) wmma::fill_fragment(acc[mf][nf], 0.f);

    const int NKT = ND/32;
#define H_LOAD(s, k0)  do {                                                    \
    _Pragma("unroll")                                                          \
    for (int l=0; l<2; l++){                                                   \
        int idx = tid + l*256;                                                 \
        int r = idx >> 2, c8 = idx & 3;                                        \
        cp16(&sm[s][0][r][c8*8], &g_textbf[(size_t)(m0+r)*ND + (k0) + c8*8]);  \
        cp16(&sm[s][1][r][c8*8], &g_w1bf  [(size_t)(n0+r)*ND + (k0) + c8*8]);  \
    } } while(0)

    H_LOAD(0, 0);
    cp_commit();
    for (int kt=0; kt<NKT; kt++){
        cp_wait<0>();
        __syncthreads();
        if (kt+1 < NKT){ H_LOAD((kt+1)&1, (kt+1)*32); cp_commit(); }
        int s = kt & 1;
#pragma unroll
        for (int ks=0; ks<2; ks++){
            wmma::fragment<wmma::matrix_a,16,16,16,__nv_bfloat16,wmma::row_major> af[2];
            wmma::fragment<wmma::matrix_b,16,16,16,__nv_bfloat16,wmma::col_major> bf[4];
#pragma unroll
            for (int mf=0;mf<2;mf++)
                wmma::load_matrix_sync(af[mf], &sm[s][0][warp_m*32+mf*16][ks*16], 40);
#pragma unroll
            for (int nf=0;nf<4;nf++)
                wmma::load_matrix_sync(bf[nf], &sm[s][1][warp_n*64+nf*16][ks*16], 40);
#pragma unroll
            for (int mf=0;mf<2;mf++)
#pragma unroll
                for (int nf=0;nf<4;nf++)
                    wmma::mma_sync(acc[mf][nf], af[mf], bf[nf], acc[mf][nf]);
        }
    }
#undef H_LOAD
    __syncthreads();   // all compute done before smem reuse

    // fused epilogue: scale by ta[m], bias, relu, dot with fc2w
    float* buf = (float*)sm;    // 64*132*4 = 33.8KB <= 40KB
    int row = tid >> 2, q = tid & 3;
#pragma unroll
    for (int half=0; half<2; half++){
        if ((warp_m >> 1) == half){
            int rbase = (warp_m & 1)*32;
#pragma unroll
            for (int mf=0;mf<2;mf++)
#pragma unroll
                for (int nf=0;nf<4;nf++)
                    wmma::store_matrix_sync(&buf[(rbase+mf*16)*132 + warp_n*64+nf*16],
                                            acc[mf][nf], 132, wmma::mem_row_major);
        }
        __syncthreads();
        int lr = half*64 + row;
        float sc = sta[lr];
        float s = 0.f;
        int cbase = q*32;
#pragma unroll
        for (int c=0;c<32;c++){
            int gn = n0 + cbase + c;
            s += fmaxf(sc*buf[row*132 + cbase + c] + fc1b[gn], 0.f) * fc2w[gn];
        }
        s += __shfl_down_sync(0xffffffffu, s, 2);
        s += __shfl_down_sync(0xffffffffu, s, 1);
        if (q == 0) g_predpart[blockIdx.y*NM + m0 + lr] = s;
        __syncthreads();
    }
}

// ---------------- vision_CLS / text_CLS : grid (NB,3)  (fp32 path) ----------------
__global__ void cls_kernel(const float* __restrict__ vision, const float* __restrict__ text){
    int b = blockIdx.x;
    int d = blockIdx.y*256 + threadIdx.x;
    float av = 0.f, at = 0.f;
    const float* vb = vision + (size_t)b*NV*ND + d;
#pragma unroll 4
    for (int v=0; v<NV; v++) av += g_va[b*NV+v] * vb[(size_t)v*ND];
    const float* tb = text + (size_t)b*NT*ND + d;
#pragma unroll 4
    for (int t=0; t<NT; t++) at += g_ta[b*NT+t] * tb[(size_t)t*ND];
    g_vcls[b*ND+d] = av * (1.f/(float)NV);
    g_tcls[b*ND+d] = at * (1.f/(float)NT);
}

// ---------------- v_emb/t_emb = fc1(CLS)  (fp32, grid (NB,8)) ----------------
__global__ void emb_kernel(const float* __restrict__ fc1w, const float* __restrict__ fc1b){
    __shared__ float sv[ND], st[ND];
    int b = blockIdx.x, tid = threadIdx.x;
    int warp = tid >> 5, lane = tid & 31;
    for (int d=tid; d<ND; d+=256){ sv[d] = g_vcls[b*ND+d]; st[d] = g_tcls[b*ND+d]; }
    __syncthreads();
    int n0 = blockIdx.y*96 + warp*12;
#pragma unroll
    for (int k=0; k<12; k++){
        int n = n0 + k;
        const float* wr = fc1w + (size_t)n*ND;
        float a=0.f, cc=0.f;
        for (int d=lane; d<ND; d+=32){ float w = wr[d]; a += w*sv[d]; cc += w*st[d]; }
        a = wred(a); cc = wred(cc);
        if (lane == 0){
            g_vemb[b*ND+n] = a + fc1b[n];
            g_temb[b*ND+n] = cc + fc1b[n];
        }
    }
}

// ---------------- per-sample masked MSE from partials ----------------
__global__ void textloss_kernel(const float* __restrict__ sent, const int* __restrict__ lens,
                                const float* __restrict__ fc2b){
    __shared__ float sred[8];
    int b = blockIdx.x, tid = threadIdx.x;
    int len = lens[b];
    float s = 0.f;
    for (int t=tid; t<NT; t+=256){
        int m = b*NT + t;
        float p = fc2b[0];
#pragma unroll
        for (int pp=0; pp<NNB; pp++) p += g_predpart[pp*NM + m];
        if (sent[m] == 0.f) p = 0.f;
        if (t < len){
            float d = p - sent[m];
            s += d*d;
        }
    }
    s = wred(s);
    if ((tid & 31) == 0) sred[tid>>5] = s;
    __syncthreads();
    if (tid < 8){
        float v = sred[tid];
#pragma unroll
        for (int o=4;o;o>>=1) v += __shfl_xor_sync(0xffu, v, o);
        if (tid == 0) g_lossb[b] = v / (float)len;
    }
}

// ---------------- heads, contrast KL, semantic branch, outputs ----------------
__global__ __launch_bounds__(1024) void final_kernel(const float* __restrict__ fc2w,
                                                     const float* __restrict__ fc2b,
                                                     const float* __restrict__ fw,
                                                     const float* __restrict__ fb,
                                                     float* __restrict__ out){
    __shared__ float s_vs[32], s_ts[32], s_inv_nv[32], s_inv_nt[32];
    __shared__ float s_c[32][32], s_sim[32][32];
    __shared__ float s_crow[32], s_srow[32];
    __shared__ float s_var_v[ND], s_var_t[ND];
    __shared__ float s_red[32];
    __shared__ float s_tile[32][129];
    __shared__ float s_scal[2];

    int tid = threadIdx.x;
    int warp = tid >> 5, lane = tid & 31;

    {
        int b = warp;
        float vs=0.f, ts=0.f, nv=0.f, nt=0.f;
        for (int d=lane; d<ND; d+=32){
            float ve = g_vemb[b*ND+d], te = g_temb[b*ND+d], w = fc2w[d];
            vs += fmaxf(ve,0.f)*w; ts += te*w; nv += ve*ve; nt += te*te;
        }
        vs = wred(vs); ts = wred(ts); nv = wred(nv); nt = wred(nt);
        if (lane == 0){
            s_vs[b] = vs + fc2b[0];
            s_ts[b] = ts + fc2b[0];
            s_inv_nv[b] = 1.f/fmaxf(sqrtf(nv), 1e-12f);
            s_inv_nt[b] = 1.f/fmaxf(sqrtf(nt), 1e-12f);
        }
    }
    __syncthreads();

    int i = tid >> 5, j = tid & 31;
    float dot = 0.f;
    for (int kc=0; kc<ND; kc+=128){
        for (int e=tid; e<32*128; e+=1024){
            int r2 = e >> 7, c2 = e & 127;
            s_tile[r2][c2] = g_temb[r2*ND + kc + c2];
        }
        __syncthreads();
#pragma unroll 8
        for (int c=0;c<128;c++)
            dot += g_vemb[i*ND + kc + c] * s_tile[j][c];
        __syncthreads();
    }
    s_sim[i][j] = expf(dot * s_inv_nv[i] * s_inv_nt[j] * 5.0f);
    s_c[i][j]   = expf(-fabsf(s_vs[i] - s_ts[j]));
    __syncthreads();

    if (tid < 32){
        float cs=0.f, ss=0.f;
        for (int jj=0;jj<32;jj++){ cs += s_c[tid][jj]; ss += s_sim[tid][jj]; }
        s_crow[tid] = cs; s_srow[tid] = ss;
    }
    __syncthreads();

    {
        float cn = s_c[i][j]/s_crow[i];
        float sn = s_sim[i][j]/s_srow[i];
        float term = cn*(logf(cn) - logf(sn));
        term = wred(term);
        if (lane == 0) s_red[warp] = term;
        __syncthreads();
        if (tid < 32){
            float v = wred(s_red[tid]);
            if (tid == 0) out[32] = v * (1.f/32.f);
        }
    }
    __syncthreads();

    if (tid < ND){
        float sx=0.f, sx2=0.f;
        for (int b=0;b<32;b++){ float x = g_vcls[b*ND+tid]; sx += x; sx2 += x*x; }
        s_var_v[tid] = (sx2 - sx*sx*(1.f/32.f))*(1.f/31.f);
        sx=0.f; sx2=0.f;
        for (int b=0;b<32;b++){ float x = g_tcls[b*ND+tid]; sx += x; sx2 += x*x; }
        s_var_t[tid] = (sx2 - sx*sx*(1.f/32.f))*(1.f/31.f);
    }
    __syncthreads();
    {
        float v = (tid < ND) ? s_var_v[tid]*s_var_v[tid] : 0.f;
        v = wred(v);
        if (lane == 0) s_red[warp] = v;
        __syncthreads();
        if (tid < 32){
            float r = wred(s_red[tid]);
            if (tid == 0) s_scal[0] = 1.f/fmaxf(sqrtf(r), 1e-12f);
        }
        __syncthreads();
        float u = (tid < ND) ? s_var_t[tid]*s_var_t[tid] : 0.f;
        u = wred(u);
        if (lane == 0) s_red[warp] = u;
        __syncthreads();
        if (tid < 32){
            float r = wred(s_red[tid]);
            if (tid == 0) s_scal[1] = 1.f/fmaxf(sqrtf(r), 1e-12f);
        }
        __syncthreads();
        if (tid < ND){ s_var_v[tid] *= s_scal[0]; s_var_t[tid] *= s_scal[1]; }
    }
    __syncthreads();

    {
        int b = warp;
        float acc = 0.f;
        for (int d=lane; d<ND; d+=32){
            float sv  = g_vcls[b*ND+d]*(1.f + s_var_v[d]);
            float st2 = g_tcls[b*ND+d]*(1.f + s_var_t[d]);
            float fcls = 0.5f*(sv*st2 + g_vemb[b*ND+d]*g_temb[b*ND+d]);
            acc += fcls*fw[d];
        }
        acc = wred(acc);
        if (lane == 0)
            out[b] = acc + fb[0] + 0.1f*fabsf(s_ts[b] - s_vs[b]) - 0.5f;
    }

    if (tid < 32){
        float v = wred(g_lossb[tid]);
        if (tid == 0) out[33] = v * (1.f/32.f);
    }
}

// ---------------- launch ----------------
extern "C" void kernel_launch(void* const* d_in, const int* in_sizes, int n_in,
                              void* d_out, int out_size){
    const float* vision = (const float*)d_in[0];
    const float* text   = (const float*)d_in[1];
    const float* sent   = (const float*)d_in[2];
    const int*   lens   = (const int*)  d_in[3];
    const float* fc1_w  = (const float*)d_in[4];
    const float* fc1_b  = (const float*)d_in[5];
    const float* fc2_w  = (const float*)d_in[6];
    const float* fc2_b  = (const float*)d_in[7];
    const float* c1w    = (const float*)d_in[8];
    const float* c1b    = (const float*)d_in[9];
    const float* c2w    = (const float*)d_in[10];
    const float* c2b    = (const float*)d_in[11];
    const float* fw     = (const float*)d_in[12];
    const float* fb     = (const float*)d_in[13];
    float* out = (float*)d_out;

    convert_prep_kernel<<<NCVT+1, 256>>>(text, vision, fc1_w, c1w, c1b, c2w, c2b);
    gemm_amap_kernel<<<dim3(2,4,NB), 256>>>();
    conv_fused_kernel<<<dim3(NCH,NB), 256>>>();
    gemm_h_kernel<<<dim3(128,NNB), 256>>>(fc1_b, fc2_w);      // 4th launch -> ncu slot
    cls_kernel<<<dim3(NB,3), 256>>>(vision, text);
    emb_kernel<<<dim3(NB,8), 256>>>(fc1_w, fc1_b);
    textloss_kernel<<<NB, 256>>>(sent, lens, fc2_b);
    final_kernel<<<1, 1024>>>(fc2_w, fc2_b, fw, fb, out);
}

// round 10
// speedup vs baseline: 3.5049x; 1.0499x over previous
#include <cuda_runtime.h>
#include <cuda_bf16.h>
#include <cstdint>
#include <mma.h>
using namespace nvcuda;

#define NB 32
#define NV 197
#define NVP 256
#define NT 512
#define ND 768
#define NM (NB*NT)       // 16384
#define NNB 6            // n-blocks in gemm_h (768/128)
#define NCH 13           // conv row-chunks of 16

// ---------------- device scratch ----------------
static __device__ float g_amap[NB*NVP*NT];
static __device__ float g_tapart[NCH*NB*NT];
static __device__ float g_ta[NM];
static __device__ float g_va[NB*NV];
static __device__ float g_vcls[NB*ND];
static __device__ float g_tcls[NB*ND];
static __device__ float g_temb[NB*ND];
static __device__ float g_vemb[NB*ND];
static __device__ float g_predpart[NNB*NM];
static __device__ float g_lossb[NB];
static __device__ float g_keff[9][25];
static __device__ float g_kbias[9];
static __device__ __nv_bfloat16 g_textbf[NM*ND];
static __device__ __nv_bfloat16 g_visbf[NB*NV*ND];
static __device__ __nv_bfloat16 g_w1bf[ND*ND];

__device__ __forceinline__ float wred(float v){
#pragma unroll
    for (int o = 16; o; o >>= 1) v += __shfl_xor_sync(0xffffffffu, v, o);
    return v;
}
__device__ __forceinline__ float sigmoidf(float x){ return 1.f/(1.f + expf(-x)); }

// ---- cp.async helpers ----
__device__ __forceinline__ void cp16(void* s, const void* g){
    unsigned int sa = (unsigned int)__cvta_generic_to_shared(s);
    asm volatile("cp.async.cg.shared.global [%0], [%1], 16;" :: "r"(sa), "l"(g));
}
__device__ __forceinline__ void cp_commit(){ asm volatile("cp.async.commit_group;"); }
template<int N> __device__ __forceinline__ void cp_wait(){
    asm volatile("cp.async.wait_group %0;" :: "n"(N));
}

// BK=64 tile geometry: stride 72 bf16 (=144B, conflict-free LDSM row spread)
#define TSTR 72
#define TILE_ELE (128*TSTR)                 // per matrix per stage (bf16 elements)
#define G_DYN (2*2*TILE_ELE*2)              // 73,728 B dynamic smem per GEMM block

// ---------------- fp32 -> bf16 conversion + conv composition (merged) ----------------
#define CT1 (NM*ND/4)
#define CT2 (CT1 + NB*NV*ND/4)
#define CT3 (CT2 + ND*ND/4)
#define NCVT (CT3/256)
__global__ void convert_prep_kernel(const float* __restrict__ text,
                                    const float* __restrict__ vision,
                                    const float* __restrict__ fc1w,
                                    const float* __restrict__ w1, const float* __restrict__ b1,
                                    const float* __restrict__ w2, const float* __restrict__ b2){
    if (blockIdx.x < NCVT){
        int p = blockIdx.x*256 + threadIdx.x;
        const float* src; __nv_bfloat16* dst; int off;
        if (p < CT1){ src = text; dst = g_textbf; off = p; }
        else if (p < CT2){ src = vision; dst = g_visbf; off = p - CT1; }
        else { src = fc1w; dst = g_w1bf; off = p - CT2; }
        float4 v = ((const float4*)src)[off];
        __nv_bfloat162* d2 = (__nv_bfloat162*)dst;
        d2[off*2]   = __floats2bfloat162_rn(v.x, v.y);
        d2[off*2+1] = __floats2bfloat162_rn(v.z, v.w);
        return;
    }
    int tid = threadIdx.x;
    if (tid < 225){
        int var = tid/25, uv = tid%25, u = uv/5, v = uv%5;
        int ri = var/3, rj = var%3;
        float s = 0.f;
        for (int d1=0; d1<3; d1++){
            if ((ri==0 && d1==0) || (ri==2 && d1==2)) continue;
            int d2 = u - d1; if (d2 < 0 || d2 > 2) continue;
            for (int e1=0; e1<3; e1++){
                if ((rj==0 && e1==0) || (rj==2 && e1==2)) continue;
                int e2 = v - e1; if (e2 < 0 || e2 > 2) continue;
                for (int c=0; c<64; c++)
                    s += w2[c*9 + d1*3 + e1] * w1[c*9 + d2*3 + e2];
            }
        }
        g_keff[var][uv] = s;
    } else if (tid < 234){
        int var = tid - 225;
        int ri = var/3, rj = var%3;
        float s = b2[0];
        for (int c=0; c<64; c++){
            float t = 0.f;
            for (int d1=0; d1<3; d1++){
                if ((ri==0 && d1==0) || (ri==2 && d1==2)) continue;
                for (int e1=0; e1<3; e1++){
                    if ((rj==0 && e1==0) || (rj==2 && e1==2)) continue;
                    t += w2[c*9 + d1*3 + e1];
                }
            }
            s += b1[c]*t;
        }
        g_kbias[var] = s;
    }
}

// ============ bf16 wmma GEMM 1 (BK=64, 2-stage, single-sync): amap = vision . text^T ============
__global__ __launch_bounds__(256,2) void gemm_amap_kernel(){
    extern __shared__ __align__(16) __nv_bfloat16 dynbf[];
    int b  = blockIdx.z;
    const __nv_bfloat16* A  = g_visbf  + (size_t)b*NV*ND;
    const __nv_bfloat16* Bp = g_textbf + (size_t)b*NT*ND;
    int m0 = blockIdx.x*128, n0 = blockIdx.y*128;
    int tid = threadIdx.x, wid = tid >> 5;
    int warp_m = wid >> 1, warp_n = wid & 1;

    wmma::fragment<wmma::accumulator,16,16,16,float> acc[2][4];
#pragma unroll
    for (int mf=0;mf<2;mf++)
#pragma unroll
        for (int nf=0;nf<4;nf++) wmma::fill_fragment(acc[mf][nf], 0.f);

    const int NKT = ND/64;   // 12
#define AMAP_LOAD(s, k0)  do {                                               \
    __nv_bfloat16* As_ = dynbf + (size_t)((s)*2+0)*TILE_ELE;                 \
    __nv_bfloat16* Bs_ = dynbf + (size_t)((s)*2+1)*TILE_ELE;                 \
    _Pragma("unroll")                                                        \
    for (int l=0; l<4; l++){                                                 \
        int q = tid + l*256;                                                 \
        int r = q >> 3, c8 = q & 7;                                          \
        int gm = m0 + r; if (gm > NV-1) gm = NV-1;                           \
        cp16(&As_[r*TSTR + c8*8], &A [(size_t)gm*ND + (k0) + c8*8]);         \
        cp16(&Bs_[r*TSTR + c8*8], &Bp[(size_t)(n0+r)*ND + (k0) + c8*8]);     \
    } } while(0)

    AMAP_LOAD(0, 0);
    cp_commit();
    for (int kt=0; kt<NKT; kt++){
        cp_wait<0>();
        __syncthreads();
        if (kt+1 < NKT){ AMAP_LOAD((kt+1)&1, (kt+1)*64); cp_commit(); }
        const __nv_bfloat16* As = dynbf + (size_t)((kt&1)*2+0)*TILE_ELE;
        const __nv_bfloat16* Bs = dynbf + (size_t)((kt&1)*2+1)*TILE_ELE;
#pragma unroll
        for (int ks=0; ks<4; ks++){
            wmma::fragment<wmma::matrix_a,16,16,16,__nv_bfloat16,wmma::row_major> af[2];
            wmma::fragment<wmma::matrix_b,16,16,16,__nv_bfloat16,wmma::col_major> bf[4];
#pragma unroll
            for (int mf=0;mf<2;mf++)
                wmma::load_matrix_sync(af[mf], &As[(warp_m*32+mf*16)*TSTR + ks*16], TSTR);
#pragma unroll
            for (int nf=0;nf<4;nf++)
                wmma::load_matrix_sync(bf[nf], &Bs[(warp_n*64+nf*16)*TSTR + ks*16], TSTR);
#pragma unroll
            for (int mf=0;mf<2;mf++)
#pragma unroll
                for (int nf=0;nf<4;nf++)
                    wmma::mma_sync(acc[mf][nf], af[mf], bf[nf], acc[mf][nf]);
        }
    }
#undef AMAP_LOAD
    float* C = g_amap + (size_t)b*NVP*NT;
#pragma unroll
    for (int mf=0;mf<2;mf++)
#pragma unroll
        for (int nf=0;nf<4;nf++)
            wmma::store_matrix_sync(&C[(size_t)(m0+warp_m*32+mf*16)*NT + n0+warp_n*64+nf*16],
                                    acc[mf][nf], NT, wmma::mem_row_major);
}

// ============ fused 5x5 conv + relu + va + ta partials ============
__global__ __launch_bounds__(256) void conv_fused_kernel(){
    __shared__ float smz[20][NT];
    __shared__ float kvs[9][25];
    __shared__ float kbs[9];
    __shared__ float rowred[16][8];
    int c = blockIdx.x;
    int b = blockIdx.y;
    int tid = threadIdx.x;
    int warp = tid >> 5, lane = tid & 31;
    if (tid < 225) ((float*)kvs)[tid] = ((const float*)g_keff)[tid];
    else if (tid >= 240 && tid < 249) kbs[tid-240] = g_kbias[tid-240];

    int i0 = c*16;
    const float* base = g_amap + (size_t)b*NVP*NT;
#pragma unroll
    for (int l=0; l<10; l++){
        int e = tid + l*256;
        int rr = e >> 7, c4 = e & 127;
        int gi = i0 - 2 + rr;
        float4 v = make_float4(0.f,0.f,0.f,0.f);
        if (gi >= 0 && gi < NV) v = *(const float4*)&base[(size_t)gi*NT + c4*4];
        *(float4*)&smz[rr][c4*4] = v;
    }
    __syncthreads();

    float rowpart[16];
#pragma unroll
    for (int rr=0;rr<16;rr++) rowpart[rr] = 0.f;

#pragma unroll
    for (int jj=0; jj<2; jj++){
        int j = tid + jj*256;
        int rj = (j==0) ? 0 : ((j==NT-1) ? 2 : 1);
        float kreg[25];
#pragma unroll
        for (int t=0;t<25;t++) kreg[t] = kvs[3+rj][t];
        float kbmid = kbs[3+rj];

        float w[5][5];
#pragma unroll
        for (int u=0;u<4;u++)
#pragma unroll
            for (int v=0;v<5;v++){
                int j2 = j + v - 2;
                w[u][v] = (j2>=0 && j2<NT) ? smz[u][j2] : 0.f;
            }
        float colsum = 0.f;
#pragma unroll
        for (int rr=0; rr<16; rr++){
#pragma unroll
            for (int v=0;v<5;v++){
                int j2 = j + v - 2;
                w[4][v] = (j2>=0 && j2<NT) ? smz[rr+4][j2] : 0.f;
            }
            int i = i0 + rr;
            if (i < NV){
                float s;
                if (i==0 || i==NV-1){
                    int var = ((i==0)?0:6) + rj;
                    s = kbs[var];
                    const float* kp = kvs[var];
#pragma unroll
                    for (int u=0;u<5;u++)
#pragma unroll
                        for (int v=0;v<5;v++) s += kp[u*5+v]*w[u][v];
                } else {
                    s = kbmid;
#pragma unroll
                    for (int u=0;u<5;u++)
#pragma unroll
                        for (int v=0;v<5;v++) s += kreg[u*5+v]*w[u][v];
                }
                s = fmaxf(s, 0.f);
                colsum += s;
                rowpart[rr] += s;
            }
#pragma unroll
            for (int u=0;u<4;u++)
#pragma unroll
                for (int v=0;v<5;v++) w[u][v] = w[u+1][v];
        }
        g_tapart[(size_t)(c*NB + b)*NT + j] = colsum;
    }
#pragma unroll
    for (int rr=0; rr<16; rr++){
        float v = wred(rowpart[rr]);
        if (lane == 0) rowred[rr][warp] = v;
    }
    __syncthreads();
    if (tid < 128){
        int rr = tid >> 3, slot = tid & 7;
        float v = rowred[rr][slot];
        v += __shfl_down_sync(0xffffffffu, v, 4, 8);
        v += __shfl_down_sync(0xffffffffu, v, 2, 8);
        v += __shfl_down_sync(0xffffffffu, v, 1, 8);
        if (slot == 0){
            int gi = i0 + rr;
            if (gi < NV) g_va[b*NV + gi] = sigmoidf(v * (1.f/(float)NT));
        }
    }
}

// ============ bf16 wmma GEMM 2 (BK=64, 2-stage, single-sync) + inline ta + pred epilogue ============
__global__ __launch_bounds__(256,2) void gemm_h_kernel(const float* __restrict__ fc1b,
                                                       const float* __restrict__ fc2w){
    extern __shared__ __align__(16) __nv_bfloat16 dynbf[];
    __shared__ float sta[128];
    int m0 = blockIdx.x*128, n0 = blockIdx.y*128;
    int tid = threadIdx.x, wid = tid >> 5;
    int warp_m = wid >> 1, warp_n = wid & 1;

    // inline ta for this block's 128 rows (from conv column partials)
    {
        int bb = m0 / NT, t0 = m0 % NT;
        if (tid < 128){
            float s = 0.f;
#pragma unroll
            for (int c=0;c<NCH;c++) s += g_tapart[(size_t)(c*NB + bb)*NT + t0 + tid];
            float v = sigmoidf(s * (1.f/(float)NV));
            sta[tid] = v;
            if (blockIdx.y == 0) g_ta[m0 + tid] = v;
        }
    }

    wmma::fragment<wmma::accumulator,16,16,16,float> acc[2][4];
#pragma unroll
    for (int mf=0;mf<2;mf++)
#pragma unroll
        for (int nf=0;nf<4;nf++) wmma::fill_fragment(acc[mf][nf], 0.f);

    const int NKT = ND/64;   // 12
#define H_LOAD(s, k0)  do {                                                    \
    __nv_bfloat16* As_ = dynbf + (size_t)((s)*2+0)*TILE_ELE;                   \
    __nv_bfloat16* Bs_ = dynbf + (size_t)((s)*2+1)*TILE_ELE;                   \
    _Pragma("unroll")                                                          \
    for (int l=0; l<4; l++){                                                   \
        int q = tid + l*256;                                                   \
        int r = q >> 3, c8 = q & 7;                                            \
        cp16(&As_[r*TSTR + c8*8], &g_textbf[(size_t)(m0+r)*ND + (k0) + c8*8]); \
        cp16(&Bs_[r*TSTR + c8*8], &g_w1bf  [(size_t)(n0+r)*ND + (k0) + c8*8]); \
    } } while(0)

    H_LOAD(0, 0);
    cp_commit();
    for (int kt=0; kt<NKT; kt++){
        cp_wait<0>();
        __syncthreads();
        if (kt+1 < NKT){ H_LOAD((kt+1)&1, (kt+1)*64); cp_commit(); }
        const __nv_bfloat16* As = dynbf + (size_t)((kt&1)*2+0)*TILE_ELE;
        const __nv_bfloat16* Bs = dynbf + (size_t)((kt&1)*2+1)*TILE_ELE;
#pragma unroll
        for (int ks=0; ks<4; ks++){
            wmma::fragment<wmma::matrix_a,16,16,16,__nv_bfloat16,wmma::row_major> af[2];
            wmma::fragment<wmma::matrix_b,16,16,16,__nv_bfloat16,wmma::col_major> bf[4];
#pragma unroll
            for (int mf=0;mf<2;mf++)
                wmma::load_matrix_sync(af[mf], &As[(warp_m*32+mf*16)*TSTR + ks*16], TSTR);
#pragma unroll
            for (int nf=0;nf<4;nf++)
                wmma::load_matrix_sync(bf[nf], &Bs[(warp_n*64+nf*16)*TSTR + ks*16], TSTR);
#pragma unroll
            for (int mf=0;mf<2;mf++)
#pragma unroll
                for (int nf=0;nf<4;nf++)
                    wmma::mma_sync(acc[mf][nf], af[mf], bf[nf], acc[mf][nf]);
        }
    }
#undef H_LOAD
    __syncthreads();   // all compute done before smem reuse

    // fused epilogue: scale by ta[m], bias, relu, dot with fc2w over these 128 columns
    float* buf = (float*)dynbf;    // need 64*132*4 = 33.8KB <= 72KB
    int row = tid >> 2, q = tid & 3;
#pragma unroll
    for (int half=0; half<2; half++){
        if ((warp_m >> 1) == half){
            int rbase = (warp_m & 1)*32;
#pragma unroll
            for (int mf=0;mf<2;mf++)
#pragma unroll
                for (int nf=0;nf<4;nf++)
                    wmma::store_matrix_sync(&buf[(rbase+mf*16)*132 + warp_n*64+nf*16],
                                            acc[mf][nf], 132, wmma::mem_row_major);
        }
        __syncthreads();
        int lr = half*64 + row;
        float sc = sta[lr];
        float s = 0.f;
        int cbase = q*32;
#pragma unroll
        for (int c=0;c<32;c++){
            int gn = n0 + cbase + c;
            s += fmaxf(sc*buf[row*132 + cbase + c] + fc1b[gn], 0.f) * fc2w[gn];
        }
        s += __shfl_down_sync(0xffffffffu, s, 2);
        s += __shfl_down_sync(0xffffffffu, s, 1);
        if (q == 0) g_predpart[blockIdx.y*NM + m0 + lr] = s;
        __syncthreads();
    }
}

// ---------------- vision_CLS / text_CLS : grid (NB,3) ----------------
__global__ void cls_kernel(const float* __restrict__ vision, const float* __restrict__ text){
    int b = blockIdx.x;
    int d = blockIdx.y*256 + threadIdx.x;
    float av = 0.f, at = 0.f;
    const float* vb = vision + (size_t)b*NV*ND + d;
#pragma unroll 4
    for (int v=0; v<NV; v++) av += g_va[b*NV+v] * vb[(size_t)v*ND];
    const float* tb = text + (size_t)b*NT*ND + d;
#pragma unroll 4
    for (int t=0; t<NT; t++) at += g_ta[b*NT+t] * tb[(size_t)t*ND];
    g_vcls[b*ND+d] = av * (1.f/(float)NV);
    g_tcls[b*ND+d] = at * (1.f/(float)NT);
}

// ---------------- v_emb/t_emb = fc1(CLS)  (fp32, grid (NB,8)) ----------------
__global__ void emb_kernel(const float* __restrict__ fc1w, const float* __restrict__ fc1b){
    __shared__ float sv[ND], st[ND];
    int b = blockIdx.x, tid = threadIdx.x;
    int warp = tid >> 5, lane = tid & 31;
    for (int d=tid; d<ND; d+=256){ sv[d] = g_vcls[b*ND+d]; st[d] = g_tcls[b*ND+d]; }
    __syncthreads();
    int n0 = blockIdx.y*96 + warp*12;
#pragma unroll
    for (int k=0; k<12; k++){
        int n = n0 + k;
        const float* wr = fc1w + (size_t)n*ND;
        float a=0.f, cc=0.f;
        for (int d=lane; d<ND; d+=32){ float w = wr[d]; a += w*sv[d]; cc += w*st[d]; }
        a = wred(a); cc = wred(cc);
        if (lane == 0){
            g_vemb[b*ND+n] = a + fc1b[n];
            g_temb[b*ND+n] = cc + fc1b[n];
        }
    }
}

// ---------------- per-sample masked MSE from partials ----------------
__global__ void textloss_kernel(const float* __restrict__ sent, const int* __restrict__ lens,
                                const float* __restrict__ fc2b){
    __shared__ float sred[8];
    int b = blockIdx.x, tid = threadIdx.x;
    int len = lens[b];
    float s = 0.f;
    for (int t=tid; t<NT; t+=256){
        int m = b*NT + t;
        float p = fc2b[0];
#pragma unroll
        for (int pp=0; pp<NNB; pp++) p += g_predpart[pp*NM + m];
        if (sent[m] == 0.f) p = 0.f;
        if (t < len){
            float d = p - sent[m];
            s += d*d;
        }
    }
    s = wred(s);
    if ((tid & 31) == 0) sred[tid>>5] = s;
    __syncthreads();
    if (tid < 8){
        float v = sred[tid];
#pragma unroll
        for (int o=4;o;o>>=1) v += __shfl_xor_sync(0xffu, v, o);
        if (tid == 0) g_lossb[b] = v / (float)len;
    }
}

// ---------------- heads, contrast KL, semantic branch, outputs ----------------
__global__ __launch_bounds__(1024) void final_kernel(const float* __restrict__ fc2w,
                                                     const float* __restrict__ fc2b,
                                                     const float* __restrict__ fw,
                                                     const float* __restrict__ fb,
                                                     float* __restrict__ out){
    __shared__ float s_vs[32], s_ts[32], s_inv_nv[32], s_inv_nt[32];
    __shared__ float s_c[32][32], s_sim[32][32];
    __shared__ float s_crow[32], s_srow[32];
    __shared__ float s_var_v[ND], s_var_t[ND];
    __shared__ float s_red[32];
    __shared__ float s_tile[32][129];
    __shared__ float s_scal[2];

    int tid = threadIdx.x;
    int warp = tid >> 5, lane = tid & 31;

    {
        int b = warp;
        float vs=0.f, ts=0.f, nv=0.f, nt=0.f;
        for (int d=lane; d<ND; d+=32){
            float ve = g_vemb[b*ND+d], te = g_temb[b*ND+d], w = fc2w[d];
            vs += fmaxf(ve,0.f)*w; ts += te*w; nv += ve*ve; nt += te*te;
        }
        vs = wred(vs); ts = wred(ts); nv = wred(nv); nt = wred(nt);
        if (lane == 0){
            s_vs[b] = vs + fc2b[0];
            s_ts[b] = ts + fc2b[0];
            s_inv_nv[b] = 1.f/fmaxf(sqrtf(nv), 1e-12f);
            s_inv_nt[b] = 1.f/fmaxf(sqrtf(nt), 1e-12f);
        }
    }
    __syncthreads();

    int i = tid >> 5, j = tid & 31;
    float dot = 0.f;
    for (int kc=0; kc<ND; kc+=128){
        for (int e=tid; e<32*128; e+=1024){
            int r2 = e >> 7, c2 = e & 127;
            s_tile[r2][c2] = g_temb[r2*ND + kc + c2];
        }
        __syncthreads();
#pragma unroll 8
        for (int c=0;c<128;c++)
            dot += g_vemb[i*ND + kc + c] * s_tile[j][c];
        __syncthreads();
    }
    s_sim[i][j] = expf(dot * s_inv_nv[i] * s_inv_nt[j] * 5.0f);
    s_c[i][j]   = expf(-fabsf(s_vs[i] - s_ts[j]));
    __syncthreads();

    if (tid < 32){
        float cs=0.f, ss=0.f;
        for (int jj=0;jj<32;jj++){ cs += s_c[tid][jj]; ss += s_sim[tid][jj]; }
        s_crow[tid] = cs; s_srow[tid] = ss;
    }
    __syncthreads();

    {
        float cn = s_c[i][j]/s_crow[i];
        float sn = s_sim[i][j]/s_srow[i];
        float term = cn*(logf(cn) - logf(sn));
        term = wred(term);
        if (lane == 0) s_red[warp] = term;
        __syncthreads();
        if (tid < 32){
            float v = wred(s_red[tid]);
            if (tid == 0) out[32] = v * (1.f/32.f);
        }
    }
    __syncthreads();

    if (tid < ND){
        float sx=0.f, sx2=0.f;
        for (int b=0;b<32;b++){ float x = g_vcls[b*ND+tid]; sx += x; sx2 += x*x; }
        s_var_v[tid] = (sx2 - sx*sx*(1.f/32.f))*(1.f/31.f);
        sx=0.f; sx2=0.f;
        for (int b=0;b<32;b++){ float x = g_tcls[b*ND+tid]; sx += x; sx2 += x*x; }
        s_var_t[tid] = (sx2 - sx*sx*(1.f/32.f))*(1.f/31.f);
    }
    __syncthreads();
    {
        float v = (tid < ND) ? s_var_v[tid]*s_var_v[tid] : 0.f;
        v = wred(v);
        if (lane == 0) s_red[warp] = v;
        __syncthreads();
        if (tid < 32){
            float r = wred(s_red[tid]);
            if (tid == 0) s_scal[0] = 1.f/fmaxf(sqrtf(r), 1e-12f);
        }
        __syncthreads();
        float u = (tid < ND) ? s_var_t[tid]*s_var_t[tid] : 0.f;
        u = wred(u);
        if (lane == 0) s_red[warp] = u;
        __syncthreads();
        if (tid < 32){
            float r = wred(s_red[tid]);
            if (tid == 0) s_scal[1] = 1.f/fmaxf(sqrtf(r), 1e-12f);
        }
        __syncthreads();
        if (tid < ND){ s_var_v[tid] *= s_scal[0]; s_var_t[tid] *= s_scal[1]; }
    }
    __syncthreads();

    {
        int b = warp;
        float acc = 0.f;
        for (int d=lane; d<ND; d+=32){
            float sv  = g_vcls[b*ND+d]*(1.f + s_var_v[d]);
            float st2 = g_tcls[b*ND+d]*(1.f + s_var_t[d]);
            float fcls = 0.5f*(sv*st2 + g_vemb[b*ND+d]*g_temb[b*ND+d]);
            acc += fcls*fw[d];
        }
        acc = wred(acc);
        if (lane == 0)
            out[b] = acc + fb[0] + 0.1f*fabsf(s_ts[b] - s_vs[b]) - 0.5f;
    }

    if (tid < 32){
        float v = wred(g_lossb[tid]);
        if (tid == 0) out[33] = v * (1.f/32.f);
    }
}

// ---------------- launch ----------------
extern "C" void kernel_launch(void* const* d_in, const int* in_sizes, int n_in,
                              void* d_out, int out_size){
    const float* vision = (const float*)d_in[0];
    const float* text   = (const float*)d_in[1];
    const float* sent   = (const float*)d_in[2];
    const int*   lens   = (const int*)  d_in[3];
    const float* fc1_w  = (const float*)d_in[4];
    const float* fc1_b  = (const float*)d_in[5];
    const float* fc2_w  = (const float*)d_in[6];
    const float* fc2_b  = (const float*)d_in[7];
    const float* c1w    = (const float*)d_in[8];
    const float* c1b    = (const float*)d_in[9];
    const float* c2w    = (const float*)d_in[10];
    const float* c2b    = (const float*)d_in[11];
    const float* fw     = (const float*)d_in[12];
    const float* fb     = (const float*)d_in[13];
    float* out = (float*)d_out;

    cudaFuncSetAttribute(gemm_amap_kernel, cudaFuncAttributeMaxDynamicSharedMemorySize, G_DYN);
    cudaFuncSetAttribute(gemm_h_kernel,    cudaFuncAttributeMaxDynamicSharedMemorySize, G_DYN);

    convert_prep_kernel<<<NCVT+1, 256>>>(text, vision, fc1_w, c1w, c1b, c2w, c2b);
    gemm_amap_kernel<<<dim3(2,4,NB), 256, G_DYN>>>();
    conv_fused_kernel<<<dim3(NCH,NB), 256>>>();
    gemm_h_kernel<<<dim3(128,NNB), 256, G_DYN>>>(fc1_b, fc2_w);   // 4th launch -> ncu slot
    cls_kernel<<<dim3(NB,3), 256>>>(vision, text);
    emb_kernel<<<dim3(NB,8), 256>>>(fc1_w, fc1_b);
    textloss_kernel<<<NB, 256>>>(sent, lens, fc2_b);
    final_kernel<<<1, 1024>>>(fc2_w, fc2_b, fw, fb, out);
}